// round 10
// baseline (speedup 1.0000x reference)
#include <cuda_runtime.h>
#include <cuda_fp16.h>
#include <cstdint>
#include <math.h>

// Router: logits = x @ W^T (N=16384, D=2048, E=64), softmax, top-2, renorm.
// Output fp32 concat: probs [N*64] | indices [N*2] | weights [N*2]
//
// R10: BM=128, 512 threads, 3-stage cp.async.bulk pipeline (2 chunks of
// latency cover), B traffic halved vs R9. Refine merged into the router
// epilogue (inline exact fp32 recompute for ambiguous rows) -> 2 kernels,
// so ncu -s5 captures the router. Numerics: W presplit fp16 hi+lo (g_B),
// x converted to fp16 in smem, chunk-local accumulator fold.

#define D_DIM 2048
#define E_DIM 64
#define BM 128
#define BK 64
#define THREADS 512
#define NCHUNK (D_DIM / BK)   // 32
#define N_ROWS 16384
#define TAU 2e-3f

// smem byte layout
#define SM_MBAR 0                                   // 3 x 8B mbarriers
#define SM_BASE 128
#define A32_STR 68                                  // floats per row (64 + pad)
#define A32_BYTES (BM * A32_STR * 4)                // 34816
#define B_STR 36                                    // u32 per expert row (32 + pad)
#define B_BYTES (2 * 64 * B_STR * 4)                // 18432
#define STAGE_BYTES (A32_BYTES + B_BYTES)           // 53248
#define NSTAGE 3
#define SM_A16 (SM_BASE + NSTAGE * STAGE_BYTES)     // 159872
#define A16_STR 36                                  // u32 per row (32 + pad)
#define A16_BYTES (BM * A16_STR * 4)                // 18432
#define SMEM_BYTES (SM_A16 + A16_BYTES)             // 178304
#define TX_BYTES (BM * BK * 4 + B_BYTES)            // 32768 + 18432 = 51200

// g_B[chunk][term][expert][B_STR u32] : permuted fp16x2 slots, smem-identical
__device__ uint32_t g_B[NCHUNK * 2 * 64 * B_STR];

__device__ __forceinline__ uint32_t smem_u32(const void* p) {
    uint32_t a;
    asm("{ .reg .u64 t; cvta.to.shared.u64 t, %1; cvt.u32.u64 %0, t; }" : "=r"(a) : "l"(p));
    return a;
}
__device__ __forceinline__ uint32_t h2pack(float a, float b) {
    __half2 h = __floats2half2_rn(a, b);
    return *(uint32_t*)&h;
}
__device__ __forceinline__ void mma_f16(float* c,
                                        uint32_t a0, uint32_t a1, uint32_t a2, uint32_t a3,
                                        uint32_t b0, uint32_t b1) {
    asm volatile(
        "mma.sync.aligned.m16n8k16.row.col.f32.f16.f16.f32 "
        "{%0,%1,%2,%3}, {%4,%5,%6,%7}, {%8,%9}, {%0,%1,%2,%3};"
        : "+f"(c[0]), "+f"(c[1]), "+f"(c[2]), "+f"(c[3])
        : "r"(a0), "r"(a1), "r"(a2), "r"(a3), "r"(b0), "r"(b1));
}
__device__ __forceinline__ void mbar_init(uint32_t m, uint32_t cnt) {
    asm volatile("mbarrier.init.shared.b64 [%0], %1;" :: "r"(m), "r"(cnt) : "memory");
}
__device__ __forceinline__ void mbar_expect(uint32_t m, uint32_t tx) {
    asm volatile("mbarrier.arrive.expect_tx.shared.b64 _, [%0], %1;" :: "r"(m), "r"(tx) : "memory");
}
__device__ __forceinline__ void bulk_g2s(uint32_t dst, const void* src, uint32_t bytes, uint32_t mbar) {
    asm volatile(
        "cp.async.bulk.shared::cluster.global.mbarrier::complete_tx::bytes [%0], [%1], %2, [%3];"
        :: "r"(dst), "l"(src), "r"(bytes), "r"(mbar) : "memory");
}
__device__ __forceinline__ void mbar_wait(uint32_t m, uint32_t parity) {
    uint32_t done;
    asm volatile(
        "{\n\t.reg .pred p;\n\t"
        "mbarrier.try_wait.parity.acquire.cta.shared::cta.b64 p, [%1], %2;\n\t"
        "selp.b32 %0, 1, 0, p;\n\t}"
        : "=r"(done) : "r"(m), "r"(parity) : "memory");
    if (!done) {
        asm volatile(
            "{\n\t.reg .pred P1;\n\t"
            "W_%=:\n\t"
            "mbarrier.try_wait.parity.acquire.cta.shared::cta.b64 P1, [%0], %1, 0x989680;\n\t"
            "@P1 bra.uni DN_%=;\n\t"
            "bra.uni W_%=;\n\t"
            "DN_%=:\n\t}"
            :: "r"(m), "r"(parity) : "memory");
    }
}

// ---- Pre-kernel: build g_B (fp16 hi/lo, permuted slots, padded rows) ----
__global__ __launch_bounds__(256, 1)
void split_w_kernel(const float* __restrict__ W)
{
    const int g = blockIdx.x * 256 + threadIdx.x;   // 0..2047
    if (g >= NCHUNK * 64) return;
    const int chunk = g >> 6;
    const int e     = g & 63;

    const float* src = W + (size_t)e * D_DIM + chunk * BK;
    float v[64];
#pragma unroll
    for (int i = 0; i < 16; i++) {
        float4 f = *(const float4*)(src + 4 * i);
        v[4 * i] = f.x; v[4 * i + 1] = f.y; v[4 * i + 2] = f.z; v[4 * i + 3] = f.w;
    }

    uint32_t hi[32], lo[32];
#pragma unroll
    for (int sub = 0; sub < 2; sub++) {
#pragma unroll
        for (int s = 0; s < 16; s++) {
            int b  = s >> 3;
            int s8 = s & 7;
            int pl = (s8 & 1) ? ((s8 >> 1) + 4) : (s8 >> 1);
            int k  = 32 * sub + b * 16 + 2 * pl;
            __half2 h = __floats2half2_rn(v[k], v[k + 1]);
            hi[sub * 16 + s] = *(uint32_t*)&h;
            float l0 = v[k]     - __low2float(h);
            float l1 = v[k + 1] - __high2float(h);
            __half2 l = __floats2half2_rn(l0, l1);
            lo[sub * 16 + s] = *(uint32_t*)&l;
        }
    }
    uint32_t* dh = g_B + (((size_t)chunk * 2 + 0) * 64 + e) * B_STR;
    uint32_t* dl = g_B + (((size_t)chunk * 2 + 1) * 64 + e) * B_STR;
#pragma unroll
    for (int i = 0; i < 8; i++) {
        *(uint4*)(dh + 4 * i) = *(uint4*)(hi + 4 * i);
        *(uint4*)(dl + 4 * i) = *(uint4*)(lo + 4 * i);
    }
}

__global__ __launch_bounds__(THREADS, 1)
void router_kernel(const float* __restrict__ x,
                   const float* __restrict__ W,
                   float* __restrict__ probs_out,
                   float* __restrict__ idx_out,
                   float* __restrict__ w_out)
{
    extern __shared__ char smem[];
    const uint32_t sbase = smem_u32(smem);

    const int tid  = threadIdx.x;
    const int wid  = tid >> 5;
    const int lane = tid & 31;
    const int m0   = blockIdx.x * BM;

    // 16 warps: 4 row groups x 4 col groups; warp tile 32x16
    const int wr = (wid & 3) * 32;
    const int wc = (wid >> 2) * 16;
    const int qr = lane >> 2;   // 0..7
    const int qc = lane & 3;    // 0..3

    // converter mapping: thread -> (row = tid>>2, lq = tid&3)
    const int crow = tid >> 2;               // 0..127
    const int clq  = tid & 3;
    const int ck0  = (clq & 1) * 4 + (clq >> 1) * 16;   // within 32-k sub-chunk

    if (tid == 0) {
        mbar_init(sbase + SM_MBAR + 0,  1);
        mbar_init(sbase + SM_MBAR + 8,  1);
        mbar_init(sbase + SM_MBAR + 16, 1);
    }
    __syncthreads();

    auto issue = [&](int chunk) {
        const int s = chunk % NSTAGE;
        const uint32_t a32 = sbase + SM_BASE + s * STAGE_BYTES;
        const uint32_t bsm = a32 + A32_BYTES;
        const uint32_t mb  = sbase + SM_MBAR + s * 8;
        if (tid == 0) {
            mbar_expect(mb, TX_BYTES);
            bulk_g2s(bsm, g_B + (size_t)chunk * 2 * 64 * B_STR, B_BYTES, mb);
        }
        if (tid < BM) {
            const float* src = x + (size_t)(m0 + tid) * D_DIM + chunk * BK;
            bulk_g2s(a32 + tid * (A32_STR * 4), src, BK * 4, mb);
        }
    };

    float accM[2][2][4];
#pragma unroll
    for (int i = 0; i < 2; i++)
#pragma unroll
        for (int j = 0; j < 2; j++)
#pragma unroll
            for (int k = 0; k < 4; k++) accM[i][j][k] = 0.0f;

    issue(0);
    issue(1);

    uint32_t* const A16 = (uint32_t*)(smem + SM_A16);

    for (int c = 0; c < NCHUNK; c++) {
        const int s = c % NSTAGE;
        if (c + 2 < NCHUNK) issue(c + 2);

        mbar_wait(sbase + SM_MBAR + s * 8, (c / NSTAGE) & 1);

        const float*    A32 = (const float*)(smem + SM_BASE + s * STAGE_BYTES);
        const uint32_t* Bh  = (const uint32_t*)(smem + SM_BASE + s * STAGE_BYTES + A32_BYTES);
        const uint32_t* Bl  = Bh + 64 * B_STR;

        // convert fp32 -> fp16 permuted tile (R8 packing), 2 sub-chunks
#pragma unroll
        for (int sub = 0; sub < 2; sub++) {
            const float* p = A32 + crow * A32_STR + 32 * sub + ck0;
            float4 f0 = *(const float4*)(p);
            float4 f1 = *(const float4*)(p + 8);
            uint4 v;
            v.x = h2pack(f0.x, f0.y);
            v.y = h2pack(f1.x, f1.y);
            v.z = h2pack(f0.z, f0.w);
            v.w = h2pack(f1.z, f1.w);
            *(uint4*)(A16 + crow * A16_STR + sub * 16 + clq * 4) = v;
        }
        __syncthreads();

        float accL[2][2][4];
#pragma unroll
        for (int i = 0; i < 2; i++)
#pragma unroll
            for (int j = 0; j < 2; j++)
#pragma unroll
                for (int k = 0; k < 4; k++) accL[i][j][k] = 0.0f;

#pragma unroll
        for (int K = 0; K < 4; K++) {
            const int so = (K >> 1) * 16 + (K & 1) * 8 + 2 * qc;

            uint32_t a[2][4];
#pragma unroll
            for (int mt = 0; mt < 2; mt++) {
                const int r0 = wr + mt * 16 + qr;
                uint2 lo2 = *(const uint2*)(A16 + r0 * A16_STR + so);
                uint2 hi2 = *(const uint2*)(A16 + (r0 + 8) * A16_STR + so);
                a[mt][0] = lo2.x; a[mt][2] = lo2.y;
                a[mt][1] = hi2.x; a[mt][3] = hi2.y;
            }
            uint2 bh[2], bl[2];
#pragma unroll
            for (int nt = 0; nt < 2; nt++) {
                const int n = wc + nt * 8 + qr;
                bh[nt] = *(const uint2*)(Bh + n * B_STR + so);
                bl[nt] = *(const uint2*)(Bl + n * B_STR + so);
            }
#pragma unroll
            for (int mt = 0; mt < 2; mt++)
#pragma unroll
                for (int nt = 0; nt < 2; nt++) {
                    mma_f16(accL[mt][nt], a[mt][0], a[mt][1], a[mt][2], a[mt][3],
                            bh[nt].x, bh[nt].y);
                    mma_f16(accL[mt][nt], a[mt][0], a[mt][1], a[mt][2], a[mt][3],
                            bl[nt].x, bl[nt].y);
                }
        }

#pragma unroll
        for (int i = 0; i < 2; i++)
#pragma unroll
            for (int j = 0; j < 2; j++)
#pragma unroll
                for (int k = 0; k < 4; k++) accM[i][j][k] += accL[i][j][k];

        __syncthreads();
    }

    // ---- stage logits into smem overlay ----
    float (*ls)[E_DIM + 2] = (float (*)[E_DIM + 2])smem;
#pragma unroll
    for (int mt = 0; mt < 2; mt++)
#pragma unroll
        for (int nt = 0; nt < 2; nt++) {
            int r  = wr + mt * 16 + qr;
            int cc = wc + nt * 8 + qc * 2;
            ls[r][cc]         = accM[mt][nt][0];
            ls[r][cc + 1]     = accM[mt][nt][1];
            ls[r + 8][cc]     = accM[mt][nt][2];
            ls[r + 8][cc + 1] = accM[mt][nt][3];
        }
    __syncthreads();

    // ---- epilogue: one warp per row (16 warps, 128 rows -> 8 each) ----
    const unsigned FULL = 0xFFFFFFFFu;

    auto wtop2 = [&](float pa, int ia, float pb, int ib,
                     float& V1, int& I1, float& V2, int& I2) {
        float v1, v2; int i1, i2;
        if (pa >= pb) { v1 = pa; i1 = ia; v2 = pb; i2 = ib; }
        else          { v1 = pb; i1 = ib; v2 = pa; i2 = ia; }
#pragma unroll
        for (int off = 16; off > 0; off >>= 1) {
            float ov1 = __shfl_xor_sync(FULL, v1, off);
            int   oi1 = __shfl_xor_sync(FULL, i1, off);
            float ov2 = __shfl_xor_sync(FULL, v2, off);
            int   oi2 = __shfl_xor_sync(FULL, i2, off);
            bool o_first = (ov1 > v1) || (ov1 == v1 && oi1 < i1);
            float n1, n2; int ni1, ni2;
            if (o_first) {
                n1 = ov1; ni1 = oi1;
                bool aa = (v1 > ov2) || (v1 == ov2 && i1 < oi2);
                if (aa) { n2 = v1;  ni2 = i1;  } else { n2 = ov2; ni2 = oi2; }
            } else {
                n1 = v1; ni1 = i1;
                bool aa = (ov1 > v2) || (ov1 == v2 && oi1 < i2);
                if (aa) { n2 = ov1; ni2 = oi1; } else { n2 = v2;  ni2 = i2;  }
            }
            v1 = n1; i1 = ni1; v2 = n2; i2 = ni2;
        }
        V1 = v1; I1 = i1; V2 = v2; I2 = i2;
    };

    for (int r = wid; r < BM; r += 16) {
        float l1 = ls[r][lane];
        float l2 = ls[r][lane + 32];

        float m = fmaxf(l1, l2);
#pragma unroll
        for (int off = 16; off > 0; off >>= 1)
            m = fmaxf(m, __shfl_xor_sync(FULL, m, off));

        float e1 = expf(l1 - m);
        float e2 = expf(l2 - m);

        float s = e1 + e2;
#pragma unroll
        for (int off = 16; off > 0; off >>= 1)
            s += __shfl_xor_sync(FULL, s, off);
        float inv = 1.0f / s;

        float pa = e1 * inv;
        float pb = e2 * inv;

        const int row = m0 + r;
        probs_out[(size_t)row * E_DIM + lane]      = pa;
        probs_out[(size_t)row * E_DIM + lane + 32] = pb;

        float v1, v2, v3, v4;
        int i1, i2, i3, i4;
        wtop2(pa, lane, pb, lane + 32, v1, i1, v2, i2);

        float pa2 = (lane == i1 || lane == i2) ? -1.0f : pa;
        float pb2 = (lane + 32 == i1 || lane + 32 == i2) ? -1.0f : pb;
        wtop2(pa2, lane, pb2, lane + 32, v3, i3, v4, i4);

        // results are warp-uniform after the butterflies
        bool ambiguous = ((v1 - v2) < TAU) || ((v2 - v3) < TAU);

        if (!ambiguous) {
            if (lane == 0) {
                float denom = v1 + v2 + 1e-9f;
                idx_out[(size_t)row * 2 + 0] = (float)i1;
                idx_out[(size_t)row * 2 + 1] = (float)i2;
                w_out[(size_t)row * 2 + 0]   = v1 / denom;
                w_out[(size_t)row * 2 + 1]   = v2 / denom;
            }
        } else {
            // inline exact fp32 recompute of 4 candidate logits
            const float* xr = x + (size_t)row * D_DIM;
            const float* w0 = W + (size_t)i1 * D_DIM;
            const float* w1 = W + (size_t)i2 * D_DIM;
            const float* w2 = W + (size_t)i3 * D_DIM;
            const float* w3 = W + (size_t)i4 * D_DIM;

            float d0 = 0.f, d1 = 0.f, d2 = 0.f, d3 = 0.f;
            for (int k = lane * 4; k < D_DIM; k += 128) {
                float4 xv = *(const float4*)(xr + k);
                float4 a  = *(const float4*)(w0 + k);
                float4 b  = *(const float4*)(w1 + k);
                float4 cc = *(const float4*)(w2 + k);
                float4 dd = *(const float4*)(w3 + k);
                d0 = fmaf(xv.x, a.x,  fmaf(xv.y, a.y,  fmaf(xv.z, a.z,  fmaf(xv.w, a.w,  d0))));
                d1 = fmaf(xv.x, b.x,  fmaf(xv.y, b.y,  fmaf(xv.z, b.z,  fmaf(xv.w, b.w,  d1))));
                d2 = fmaf(xv.x, cc.x, fmaf(xv.y, cc.y, fmaf(xv.z, cc.z, fmaf(xv.w, cc.w, d2))));
                d3 = fmaf(xv.x, dd.x, fmaf(xv.y, dd.y, fmaf(xv.z, dd.z, fmaf(xv.w, dd.w, d3))));
            }
#pragma unroll
            for (int off = 16; off > 0; off >>= 1) {
                d0 += __shfl_xor_sync(FULL, d0, off);
                d1 += __shfl_xor_sync(FULL, d1, off);
                d2 += __shfl_xor_sync(FULL, d2, off);
                d3 += __shfl_xor_sync(FULL, d3, off);
            }
            if (lane == 0) {
                float l[4]  = {d0, d1, d2, d3};
                int   id[4] = {i1, i2, i3, i4};
#pragma unroll
                for (int i = 0; i < 2; i++) {
                    int best = i;
#pragma unroll
                    for (int j = i + 1; j < 4; j++) {
                        if ((l[j] > l[best]) || (l[j] == l[best] && id[j] < id[best])) best = j;
                    }
                    float tl = l[i]; l[i] = l[best]; l[best] = tl;
                    int ti = id[i]; id[i] = id[best]; id[best] = ti;
                }
                float mm  = fmaxf(l[0], l[1]);
                float ee1 = expf(l[0] - mm);
                float ee2 = expf(l[1] - mm);
                float w1v = ee1 / (ee1 + ee2);
                idx_out[(size_t)row * 2 + 0] = (float)id[0];
                idx_out[(size_t)row * 2 + 1] = (float)id[1];
                w_out[(size_t)row * 2 + 0]   = w1v;
                w_out[(size_t)row * 2 + 1]   = 1.0f - w1v;
            }
        }
    }
}

extern "C" void kernel_launch(void* const* d_in, const int* in_sizes, int n_in,
                              void* d_out, int out_size)
{
    const float* x = (const float*)d_in[0];
    const float* W = (const float*)d_in[1];
    const int N = in_sizes[0] / D_DIM;   // 16384

    float* out   = (float*)d_out;
    float* probs = out;
    float* idx   = out + (size_t)N * E_DIM;
    float* wts   = out + (size_t)N * E_DIM + (size_t)N * 2;

    cudaFuncSetAttribute(router_kernel,
                         cudaFuncAttributeMaxDynamicSharedMemorySize, SMEM_BYTES);

    split_w_kernel<<<8, 256>>>(W);
    router_kernel<<<N / BM, THREADS, SMEM_BYTES>>>(x, W, probs, idx, wts);
}

// round 11
// speedup vs baseline: 1.0667x; 1.0667x over previous
#include <cuda_runtime.h>
#include <cuda_fp16.h>
#include <cstdint>
#include <math.h>

// Router: logits = x @ W^T (N=16384, D=2048, E=64), softmax, top-2, renorm.
// Output fp32 concat: probs [N*64] | indices [N*2] | weights [N*2]
//
// R11: three kernels.
//  1) split_w: W -> g_B (fp16 hi+lo, permuted slots, stride-36 rows; one
//     contiguous 18KB blob per chunk).  [unchanged layout from R10]
//  2) prep_x: streaming conversion x (fp32) -> g_x16 (fp16, same permuted
//     slot layout, stride-36 rows; one contiguous 18KB blob per
//     (row-block, chunk)).  Runs at DRAM rate (no sync, no reuse).
//  3) router: per chunk, TWO 18KB cp.async.bulk copies (A blob + B blob),
//     4-stage pipeline with full(tx)/consumed(count=16) mbarriers, NO
//     __syncthreads in the mainloop (warps free-run). Frags + fp16
//     m16n8k16 MMA identical to the R8-validated path; chunk-local fold;
//     inline exact-fp32 refine for ambiguous rows.

#define D_DIM 2048
#define E_DIM 64
#define BM 128
#define BK 64
#define THREADS 512
#define NCHUNK (D_DIM / BK)   // 32
#define NSTAGE 4
#define N_ROWS 16384
#define NBLK (N_ROWS / BM)    // 128
#define TAU 2e-3f

#define STR 36                                   // u32 stride per row
#define A_U32 (BM * STR)                         // 4608  (18432 B)
#define B_U32 (2 * 64 * STR)                     // 4608  (18432 B)
#define A_BYTES (A_U32 * 4)
#define B_BYTES (B_U32 * 4)
#define STAGE_BYTES (A_BYTES + B_BYTES)          // 36864
#define SM_BASE 1024
#define SMEM_BYTES (SM_BASE + NSTAGE * STAGE_BYTES)   // 148480
#define TX_BYTES STAGE_BYTES

// g_x16[nblk][chunk] : 18KB blob = 128 rows x 36 u32 (permuted fp16x2 slots)
__device__ uint32_t g_x16[(size_t)NBLK * NCHUNK * A_U32];
// g_B[chunk] : 18KB blob = [term hi/lo][64 experts][36 u32]
__device__ uint32_t g_B[(size_t)NCHUNK * B_U32];

__device__ __forceinline__ uint32_t smem_u32(const void* p) {
    uint32_t a;
    asm("{ .reg .u64 t; cvta.to.shared.u64 t, %1; cvt.u32.u64 %0, t; }" : "=r"(a) : "l"(p));
    return a;
}
__device__ __forceinline__ uint32_t h2pack(float a, float b) {
    __half2 h = __floats2half2_rn(a, b);
    return *(uint32_t*)&h;
}
__device__ __forceinline__ void mma_f16(float* c,
                                        uint32_t a0, uint32_t a1, uint32_t a2, uint32_t a3,
                                        uint32_t b0, uint32_t b1) {
    asm volatile(
        "mma.sync.aligned.m16n8k16.row.col.f32.f16.f16.f32 "
        "{%0,%1,%2,%3}, {%4,%5,%6,%7}, {%8,%9}, {%0,%1,%2,%3};"
        : "+f"(c[0]), "+f"(c[1]), "+f"(c[2]), "+f"(c[3])
        : "r"(a0), "r"(a1), "r"(a2), "r"(a3), "r"(b0), "r"(b1));
}
__device__ __forceinline__ void mbar_init(uint32_t m, uint32_t cnt) {
    asm volatile("mbarrier.init.shared.b64 [%0], %1;" :: "r"(m), "r"(cnt) : "memory");
}
__device__ __forceinline__ void mbar_arrive(uint32_t m) {
    asm volatile("mbarrier.arrive.shared.b64 _, [%0];" :: "r"(m) : "memory");
}
__device__ __forceinline__ void mbar_expect(uint32_t m, uint32_t tx) {
    asm volatile("mbarrier.arrive.expect_tx.shared.b64 _, [%0], %1;" :: "r"(m), "r"(tx) : "memory");
}
__device__ __forceinline__ void bulk_g2s(uint32_t dst, const void* src, uint32_t bytes, uint32_t mbar) {
    asm volatile(
        "cp.async.bulk.shared::cluster.global.mbarrier::complete_tx::bytes [%0], [%1], %2, [%3];"
        :: "r"(dst), "l"(src), "r"(bytes), "r"(mbar) : "memory");
}
__device__ __forceinline__ void mbar_wait(uint32_t m, uint32_t parity) {
    uint32_t done;
    asm volatile(
        "{\n\t.reg .pred p;\n\t"
        "mbarrier.try_wait.parity.acquire.cta.shared::cta.b64 p, [%1], %2;\n\t"
        "selp.b32 %0, 1, 0, p;\n\t}"
        : "=r"(done) : "r"(m), "r"(parity) : "memory");
    if (!done) {
        asm volatile(
            "{\n\t.reg .pred P1;\n\t"
            "W_%=:\n\t"
            "mbarrier.try_wait.parity.acquire.cta.shared::cta.b64 P1, [%0], %1, 0x989680;\n\t"
            "@P1 bra.uni DN_%=;\n\t"
            "bra.uni W_%=;\n\t"
            "DN_%=:\n\t}"
            :: "r"(m), "r"(parity) : "memory");
    }
}

// ---- Kernel 1: split W into g_B (fp16 hi/lo, permuted slots) ----
__global__ __launch_bounds__(256, 1)
void split_w_kernel(const float* __restrict__ W)
{
    const int g = blockIdx.x * 256 + threadIdx.x;   // 0..2047
    if (g >= NCHUNK * 64) return;
    const int chunk = g >> 6;
    const int e     = g & 63;

    const float* src = W + (size_t)e * D_DIM + chunk * BK;
    float v[64];
#pragma unroll
    for (int i = 0; i < 16; i++) {
        float4 f = *(const float4*)(src + 4 * i);
        v[4 * i] = f.x; v[4 * i + 1] = f.y; v[4 * i + 2] = f.z; v[4 * i + 3] = f.w;
    }

    uint32_t hi[32], lo[32];
#pragma unroll
    for (int sub = 0; sub < 2; sub++) {
#pragma unroll
        for (int s = 0; s < 16; s++) {
            int b  = s >> 3;
            int s8 = s & 7;
            int pl = (s8 & 1) ? ((s8 >> 1) + 4) : (s8 >> 1);
            int k  = 32 * sub + b * 16 + 2 * pl;
            __half2 h = __floats2half2_rn(v[k], v[k + 1]);
            hi[sub * 16 + s] = *(uint32_t*)&h;
            float l0 = v[k]     - __low2float(h);
            float l1 = v[k + 1] - __high2float(h);
            __half2 l = __floats2half2_rn(l0, l1);
            lo[sub * 16 + s] = *(uint32_t*)&l;
        }
    }
    uint32_t* dh = g_B + (size_t)chunk * B_U32 + (0 * 64 + e) * STR;
    uint32_t* dl = g_B + (size_t)chunk * B_U32 + (1 * 64 + e) * STR;
#pragma unroll
    for (int i = 0; i < 8; i++) {
        *(uint4*)(dh + 4 * i) = *(uint4*)(hi + 4 * i);
        *(uint4*)(dl + 4 * i) = *(uint4*)(lo + 4 * i);
    }
}

// ---- Kernel 2: streaming x -> g_x16 (fp16, permuted slots, padded rows) ----
// grid = NBLK*NCHUNK blocks of 512 threads; block (nblk, chunk) builds one
// 18KB blob. Thread (lrow = tid>>2, clq = tid&3) handles 8 k-values per sub.
__global__ __launch_bounds__(512, 2)
void prep_x_kernel(const float* __restrict__ x)
{
    const int chunk = blockIdx.x & (NCHUNK - 1);
    const int nblk  = blockIdx.x >> 5;
    const int tid   = threadIdx.x;
    const int lrow  = tid >> 2;
    const int clq   = tid & 3;
    const int ck0   = (clq & 1) * 4 + (clq >> 1) * 16;

    const float* src = x + (size_t)(nblk * BM + lrow) * D_DIM + chunk * BK;
    uint32_t* dst = g_x16 + ((size_t)(nblk * NCHUNK + chunk) * BM + lrow) * STR;

#pragma unroll
    for (int sub = 0; sub < 2; sub++) {
        const float* p = src + 32 * sub + ck0;
        float4 f0 = *(const float4*)(p);
        float4 f1 = *(const float4*)(p + 8);
        uint4 v;
        v.x = h2pack(f0.x, f0.y);
        v.y = h2pack(f1.x, f1.y);
        v.z = h2pack(f0.z, f0.w);
        v.w = h2pack(f1.z, f1.w);
        *(uint4*)(dst + sub * 16 + clq * 4) = v;
    }
}

// ---- Kernel 3: router GEMM + softmax + top-2 (+ inline exact refine) ----
__global__ __launch_bounds__(THREADS, 1)
void router_kernel(const float* __restrict__ x,
                   const float* __restrict__ W,
                   float* __restrict__ probs_out,
                   float* __restrict__ idx_out,
                   float* __restrict__ w_out)
{
    extern __shared__ char smem[];
    const uint32_t sbase = smem_u32(smem);

    const int tid  = threadIdx.x;
    const int wid  = tid >> 5;
    const int lane = tid & 31;
    const int m0   = blockIdx.x * BM;
    const int nblk = blockIdx.x;

    // 16 warps: 4 row groups x 4 col groups; warp tile 32x16
    const int wr = (wid & 3) * 32;
    const int wc = (wid >> 2) * 16;
    const int qr = lane >> 2;
    const int qc = lane & 3;

    // mbarriers: full[s] at sbase+ s*8 (count 1, tx); consumed[s] at +64+s*8 (count 16)
    if (tid == 0) {
#pragma unroll
        for (int s = 0; s < NSTAGE; s++) {
            mbar_init(sbase + s * 8, 1);
            mbar_init(sbase + 64 + s * 8, 16);
        }
    }
    __syncthreads();

    auto issue = [&](int chunk) {
        const int s = chunk & (NSTAGE - 1);
        const uint32_t stg = sbase + SM_BASE + s * STAGE_BYTES;
        const uint32_t mb  = sbase + s * 8;
        mbar_expect(mb, TX_BYTES);
        bulk_g2s(stg, g_x16 + (size_t)(nblk * NCHUNK + chunk) * A_U32, A_BYTES, mb);
        bulk_g2s(stg + A_BYTES, g_B + (size_t)chunk * B_U32, B_BYTES, mb);
    };

    if (tid == 0) {
#pragma unroll
        for (int c = 0; c < NSTAGE; c++) issue(c);
    }

    float accM[2][2][4];
#pragma unroll
    for (int i = 0; i < 2; i++)
#pragma unroll
        for (int j = 0; j < 2; j++)
#pragma unroll
            for (int k = 0; k < 4; k++) accM[i][j][k] = 0.0f;

    for (int c = 0; c < NCHUNK; c++) {
        const int s = c & (NSTAGE - 1);
        const int r = c >> 2;              // round

        mbar_wait(sbase + s * 8, r & 1);   // stage full

        const uint32_t* A16 = (const uint32_t*)(smem + SM_BASE + s * STAGE_BYTES);
        const uint32_t* Bh  = A16 + A_U32;
        const uint32_t* Bl  = Bh + 64 * STR;

        float accL[2][2][4];
#pragma unroll
        for (int i = 0; i < 2; i++)
#pragma unroll
            for (int j = 0; j < 2; j++)
#pragma unroll
                for (int k = 0; k < 4; k++) accL[i][j][k] = 0.0f;

#pragma unroll
        for (int K = 0; K < 4; K++) {
            const int so = (K >> 1) * 16 + (K & 1) * 8 + 2 * qc;

            uint32_t a[2][4];
#pragma unroll
            for (int mt = 0; mt < 2; mt++) {
                const int r0 = wr + mt * 16 + qr;
                uint2 lo2 = *(const uint2*)(A16 + r0 * STR + so);
                uint2 hi2 = *(const uint2*)(A16 + (r0 + 8) * STR + so);
                a[mt][0] = lo2.x; a[mt][2] = lo2.y;
                a[mt][1] = hi2.x; a[mt][3] = hi2.y;
            }
            uint2 bh[2], bl[2];
#pragma unroll
            for (int nt = 0; nt < 2; nt++) {
                const int n = wc + nt * 8 + qr;
                bh[nt] = *(const uint2*)(Bh + n * STR + so);
                bl[nt] = *(const uint2*)(Bl + n * STR + so);
            }
#pragma unroll
            for (int mt = 0; mt < 2; mt++)
#pragma unroll
                for (int nt = 0; nt < 2; nt++) {
                    mma_f16(accL[mt][nt], a[mt][0], a[mt][1], a[mt][2], a[mt][3],
                            bh[nt].x, bh[nt].y);
                    mma_f16(accL[mt][nt], a[mt][0], a[mt][1], a[mt][2], a[mt][3],
                            bl[nt].x, bl[nt].y);
                }
        }

#pragma unroll
        for (int i = 0; i < 2; i++)
#pragma unroll
            for (int j = 0; j < 2; j++)
#pragma unroll
                for (int k = 0; k < 4; k++) accM[i][j][k] += accL[i][j][k];

        // this warp is done with stage s for round r
        if (lane == 0) mbar_arrive(sbase + 64 + s * 8);

        // producer: refill stage s with chunk c+NSTAGE once all 16 warps done
        if (tid == 0 && c + NSTAGE < NCHUNK) {
            mbar_wait(sbase + 64 + s * 8, r & 1);
            issue(c + NSTAGE);
        }
    }

    __syncthreads();   // all MMA reads done before overlaying smem

    // ---- stage logits into smem overlay ----
    float (*ls)[E_DIM + 2] = (float (*)[E_DIM + 2])smem;
#pragma unroll
    for (int mt = 0; mt < 2; mt++)
#pragma unroll
        for (int nt = 0; nt < 2; nt++) {
            int rr = wr + mt * 16 + qr;
            int cc = wc + nt * 8 + qc * 2;
            ls[rr][cc]         = accM[mt][nt][0];
            ls[rr][cc + 1]     = accM[mt][nt][1];
            ls[rr + 8][cc]     = accM[mt][nt][2];
            ls[rr + 8][cc + 1] = accM[mt][nt][3];
        }
    __syncthreads();

    // ---- epilogue: one warp per row (16 warps, 128 rows -> 8 each) ----
    const unsigned FULL = 0xFFFFFFFFu;

    auto wtop2 = [&](float pa, int ia, float pb, int ib,
                     float& V1, int& I1, float& V2, int& I2) {
        float v1, v2; int i1, i2;
        if (pa >= pb) { v1 = pa; i1 = ia; v2 = pb; i2 = ib; }
        else          { v1 = pb; i1 = ib; v2 = pa; i2 = ia; }
#pragma unroll
        for (int off = 16; off > 0; off >>= 1) {
            float ov1 = __shfl_xor_sync(FULL, v1, off);
            int   oi1 = __shfl_xor_sync(FULL, i1, off);
            float ov2 = __shfl_xor_sync(FULL, v2, off);
            int   oi2 = __shfl_xor_sync(FULL, i2, off);
            bool o_first = (ov1 > v1) || (ov1 == v1 && oi1 < i1);
            float n1, n2; int ni1, ni2;
            if (o_first) {
                n1 = ov1; ni1 = oi1;
                bool aa = (v1 > ov2) || (v1 == ov2 && i1 < oi2);
                if (aa) { n2 = v1;  ni2 = i1;  } else { n2 = ov2; ni2 = oi2; }
            } else {
                n1 = v1; ni1 = i1;
                bool aa = (ov1 > v2) || (ov1 == v2 && oi1 < i2);
                if (aa) { n2 = ov1; ni2 = oi1; } else { n2 = v2;  ni2 = i2;  }
            }
            v1 = n1; i1 = ni1; v2 = n2; i2 = ni2;
        }
        V1 = v1; I1 = i1; V2 = v2; I2 = i2;
    };

    for (int rrow = wid; rrow < BM; rrow += 16) {
        float l1 = ls[rrow][lane];
        float l2 = ls[rrow][lane + 32];

        float m = fmaxf(l1, l2);
#pragma unroll
        for (int off = 16; off > 0; off >>= 1)
            m = fmaxf(m, __shfl_xor_sync(FULL, m, off));

        float e1 = expf(l1 - m);
        float e2 = expf(l2 - m);

        float s = e1 + e2;
#pragma unroll
        for (int off = 16; off > 0; off >>= 1)
            s += __shfl_xor_sync(FULL, s, off);
        float inv = 1.0f / s;

        float pa = e1 * inv;
        float pb = e2 * inv;

        const int row = m0 + rrow;
        probs_out[(size_t)row * E_DIM + lane]      = pa;
        probs_out[(size_t)row * E_DIM + lane + 32] = pb;

        float v1, v2, v3, v4;
        int i1, i2, i3, i4;
        wtop2(pa, lane, pb, lane + 32, v1, i1, v2, i2);

        float pa2 = (lane == i1 || lane == i2) ? -1.0f : pa;
        float pb2 = (lane + 32 == i1 || lane + 32 == i2) ? -1.0f : pb;
        wtop2(pa2, lane, pb2, lane + 32, v3, i3, v4, i4);

        bool ambiguous = ((v1 - v2) < TAU) || ((v2 - v3) < TAU);

        if (!ambiguous) {
            if (lane == 0) {
                float denom = v1 + v2 + 1e-9f;
                idx_out[(size_t)row * 2 + 0] = (float)i1;
                idx_out[(size_t)row * 2 + 1] = (float)i2;
                w_out[(size_t)row * 2 + 0]   = v1 / denom;
                w_out[(size_t)row * 2 + 1]   = v2 / denom;
            }
        } else {
            const float* xr = x + (size_t)row * D_DIM;
            const float* w0 = W + (size_t)i1 * D_DIM;
            const float* w1 = W + (size_t)i2 * D_DIM;
            const float* w2 = W + (size_t)i3 * D_DIM;
            const float* w3 = W + (size_t)i4 * D_DIM;

            float d0 = 0.f, d1 = 0.f, d2 = 0.f, d3 = 0.f;
            for (int k = lane * 4; k < D_DIM; k += 128) {
                float4 xv = *(const float4*)(xr + k);
                float4 a  = *(const float4*)(w0 + k);
                float4 b  = *(const float4*)(w1 + k);
                float4 cc = *(const float4*)(w2 + k);
                float4 dd = *(const float4*)(w3 + k);
                d0 = fmaf(xv.x, a.x,  fmaf(xv.y, a.y,  fmaf(xv.z, a.z,  fmaf(xv.w, a.w,  d0))));
                d1 = fmaf(xv.x, b.x,  fmaf(xv.y, b.y,  fmaf(xv.z, b.z,  fmaf(xv.w, b.w,  d1))));
                d2 = fmaf(xv.x, cc.x, fmaf(xv.y, cc.y, fmaf(xv.z, cc.z, fmaf(xv.w, cc.w, d2))));
                d3 = fmaf(xv.x, dd.x, fmaf(xv.y, dd.y, fmaf(xv.z, dd.z, fmaf(xv.w, dd.w, d3))));
            }
#pragma unroll
            for (int off = 16; off > 0; off >>= 1) {
                d0 += __shfl_xor_sync(FULL, d0, off);
                d1 += __shfl_xor_sync(FULL, d1, off);
                d2 += __shfl_xor_sync(FULL, d2, off);
                d3 += __shfl_xor_sync(FULL, d3, off);
            }
            if (lane == 0) {
                float l[4]  = {d0, d1, d2, d3};
                int   id[4] = {i1, i2, i3, i4};
#pragma unroll
                for (int i = 0; i < 2; i++) {
                    int best = i;
#pragma unroll
                    for (int j = i + 1; j < 4; j++) {
                        if ((l[j] > l[best]) || (l[j] == l[best] && id[j] < id[best])) best = j;
                    }
                    float tl = l[i]; l[i] = l[best]; l[best] = tl;
                    int ti = id[i]; id[i] = id[best]; id[best] = ti;
                }
                float mm  = fmaxf(l[0], l[1]);
                float ee1 = expf(l[0] - mm);
                float ee2 = expf(l[1] - mm);
                float w1v = ee1 / (ee1 + ee2);
                idx_out[(size_t)row * 2 + 0] = (float)id[0];
                idx_out[(size_t)row * 2 + 1] = (float)id[1];
                w_out[(size_t)row * 2 + 0]   = w1v;
                w_out[(size_t)row * 2 + 1]   = 1.0f - w1v;
            }
        }
    }
}

extern "C" void kernel_launch(void* const* d_in, const int* in_sizes, int n_in,
                              void* d_out, int out_size)
{
    const float* x = (const float*)d_in[0];
    const float* W = (const float*)d_in[1];
    const int N = in_sizes[0] / D_DIM;   // 16384

    float* out   = (float*)d_out;
    float* probs = out;
    float* idx   = out + (size_t)N * E_DIM;
    float* wts   = out + (size_t)N * E_DIM + (size_t)N * 2;

    cudaFuncSetAttribute(router_kernel,
                         cudaFuncAttributeMaxDynamicSharedMemorySize, SMEM_BYTES);

    split_w_kernel<<<8, 256>>>(W);
    prep_x_kernel<<<NBLK * NCHUNK, 512>>>(x);
    router_kernel<<<N / BM, THREADS, SMEM_BYTES>>>(x, W, probs, idx, wts);
}

// round 12
// speedup vs baseline: 1.2623x; 1.1833x over previous
#include <cuda_runtime.h>
#include <cuda_fp16.h>
#include <cstdint>
#include <math.h>

// Router: logits = x @ W^T (N=16384, D=2048, E=64), softmax, top-2, renorm.
// Output fp32 concat: probs [N*64] | indices [N*2] | weights [N*2]
//
// R12: two kernels.
//  1) prep: streams x (fp32) -> g_x16 (fp16, permuted slots, stride-36 rows;
//     one contiguous 9KB blob per (64-row block, chunk)). Blocks 0-7 also
//     build g_B (W -> fp16 single term, same layout; lo term DROPPED --
//     error budget covered by measured 1.94e-4 x-rounding + quadrature).
//  2) router: BM=64, 256 thr, 4-stage pipeline, per chunk TWO 9KB
//     cp.async.bulk copies; full(tx)/consumed(count=8) mbarriers, no
//     __syncthreads in mainloop. 74KB smem -> 2+ CTAs/SM. fp16 m16n8k16,
//     chunk-local fold, inline exact-fp32 refine for ambiguous rows.

#define D_DIM 2048
#define E_DIM 64
#define BM 64
#define BK 64
#define THREADS 256
#define NCHUNK (D_DIM / BK)   // 32
#define NSTAGE 4
#define N_ROWS 16384
#define NBLK (N_ROWS / BM)    // 256
#define TAU 2e-3f

#define STR 36                                   // u32 stride per row
#define A_U32 (BM * STR)                         // 2304  (9216 B)
#define B_U32 (64 * STR)                         // 2304  (9216 B)
#define A_BYTES (A_U32 * 4)
#define B_BYTES (B_U32 * 4)
#define STAGE_BYTES (A_BYTES + B_BYTES)          // 18432
#define SM_BASE 1024
#define SMEM_BYTES (SM_BASE + NSTAGE * STAGE_BYTES)   // 74752
#define TX_BYTES STAGE_BYTES

// g_x16[nb64][chunk] : 9KB blob = 64 rows x 36 u32 (permuted fp16x2 slots)
__device__ uint32_t g_x16[(size_t)NBLK * NCHUNK * A_U32];
// g_B[chunk] : 9KB blob = 64 experts x 36 u32 (fp16, single term)
__device__ uint32_t g_B[(size_t)NCHUNK * B_U32];

__device__ __forceinline__ uint32_t smem_u32(const void* p) {
    uint32_t a;
    asm("{ .reg .u64 t; cvta.to.shared.u64 t, %1; cvt.u32.u64 %0, t; }" : "=r"(a) : "l"(p));
    return a;
}
__device__ __forceinline__ uint32_t h2pack(float a, float b) {
    __half2 h = __floats2half2_rn(a, b);
    return *(uint32_t*)&h;
}
__device__ __forceinline__ void mma_f16(float* c,
                                        uint32_t a0, uint32_t a1, uint32_t a2, uint32_t a3,
                                        uint32_t b0, uint32_t b1) {
    asm volatile(
        "mma.sync.aligned.m16n8k16.row.col.f32.f16.f16.f32 "
        "{%0,%1,%2,%3}, {%4,%5,%6,%7}, {%8,%9}, {%0,%1,%2,%3};"
        : "+f"(c[0]), "+f"(c[1]), "+f"(c[2]), "+f"(c[3])
        : "r"(a0), "r"(a1), "r"(a2), "r"(a3), "r"(b0), "r"(b1));
}
__device__ __forceinline__ void mbar_init(uint32_t m, uint32_t cnt) {
    asm volatile("mbarrier.init.shared.b64 [%0], %1;" :: "r"(m), "r"(cnt) : "memory");
}
__device__ __forceinline__ void mbar_arrive(uint32_t m) {
    asm volatile("mbarrier.arrive.shared.b64 _, [%0];" :: "r"(m) : "memory");
}
__device__ __forceinline__ void mbar_expect(uint32_t m, uint32_t tx) {
    asm volatile("mbarrier.arrive.expect_tx.shared.b64 _, [%0], %1;" :: "r"(m), "r"(tx) : "memory");
}
__device__ __forceinline__ void bulk_g2s(uint32_t dst, const void* src, uint32_t bytes, uint32_t mbar) {
    asm volatile(
        "cp.async.bulk.shared::cluster.global.mbarrier::complete_tx::bytes [%0], [%1], %2, [%3];"
        :: "r"(dst), "l"(src), "r"(bytes), "r"(mbar) : "memory");
}
__device__ __forceinline__ void mbar_wait(uint32_t m, uint32_t parity) {
    uint32_t done;
    asm volatile(
        "{\n\t.reg .pred p;\n\t"
        "mbarrier.try_wait.parity.acquire.cta.shared::cta.b64 p, [%1], %2;\n\t"
        "selp.b32 %0, 1, 0, p;\n\t}"
        : "=r"(done) : "r"(m), "r"(parity) : "memory");
    if (!done) {
        asm volatile(
            "{\n\t.reg .pred P1;\n\t"
            "W_%=:\n\t"
            "mbarrier.try_wait.parity.acquire.cta.shared::cta.b64 P1, [%0], %1, 0x989680;\n\t"
            "@P1 bra.uni DN_%=;\n\t"
            "bra.uni W_%=;\n\t"
            "DN_%=:\n\t}"
            :: "r"(m), "r"(parity) : "memory");
    }
}

// ---- Kernel 1: prep. grid 8192 x 256 threads.
// Each block builds one g_x16 blob (nb64 = b>>5, chunk = b&31).
// Blocks 0-7 additionally build g_B (2048 (chunk,expert) items).
__global__ __launch_bounds__(256, 4)
void prep_kernel(const float* __restrict__ x, const float* __restrict__ W)
{
    const int b     = blockIdx.x;
    const int tid   = threadIdx.x;
    const int chunk = b & (NCHUNK - 1);
    const int nb    = b >> 5;

    // x conversion: thread -> (row = tid>>2, quad = tid&3)
    {
        const int lrow = tid >> 2;
        const int clq  = tid & 3;
        const int ck0  = (clq & 1) * 4 + (clq >> 1) * 16;

        const float* src = x + (size_t)(nb * BM + lrow) * D_DIM + chunk * BK;
        uint32_t* dst = g_x16 + ((size_t)b * BM + lrow) * STR;

#pragma unroll
        for (int sub = 0; sub < 2; sub++) {
            const float* p = src + 32 * sub + ck0;
            float4 f0 = *(const float4*)(p);
            float4 f1 = *(const float4*)(p + 8);
            uint4 v;
            v.x = h2pack(f0.x, f0.y);
            v.y = h2pack(f1.x, f1.y);
            v.z = h2pack(f0.z, f0.w);
            v.w = h2pack(f1.z, f1.w);
            *(uint4*)(dst + sub * 16 + clq * 4) = v;
        }
    }

    // W split (single fp16 term): blocks 0-7, 256 threads each -> 2048 items
    if (b < 8) {
        const int g  = b * 256 + tid;       // 0..2047
        const int wc = g >> 6;              // chunk
        const int e  = g & 63;

        const float* src = W + (size_t)e * D_DIM + wc * BK;
        float v[64];
#pragma unroll
        for (int i = 0; i < 16; i++) {
            float4 f = *(const float4*)(src + 4 * i);
            v[4 * i] = f.x; v[4 * i + 1] = f.y; v[4 * i + 2] = f.z; v[4 * i + 3] = f.w;
        }
        uint32_t hi[32];
#pragma unroll
        for (int sub = 0; sub < 2; sub++) {
#pragma unroll
            for (int s = 0; s < 16; s++) {
                int bb = s >> 3;
                int s8 = s & 7;
                int pl = (s8 & 1) ? ((s8 >> 1) + 4) : (s8 >> 1);
                int k  = 32 * sub + bb * 16 + 2 * pl;
                hi[sub * 16 + s] = h2pack(v[k], v[k + 1]);
            }
        }
        uint32_t* dh = g_B + (size_t)wc * B_U32 + e * STR;
#pragma unroll
        for (int i = 0; i < 8; i++)
            *(uint4*)(dh + 4 * i) = *(uint4*)(hi + 4 * i);
    }
}

// ---- Kernel 2: router GEMM + softmax + top-2 (+ inline exact refine) ----
__global__ __launch_bounds__(THREADS, 1)
void router_kernel(const float* __restrict__ x,
                   const float* __restrict__ W,
                   float* __restrict__ probs_out,
                   float* __restrict__ idx_out,
                   float* __restrict__ w_out)
{
    extern __shared__ char smem[];
    const uint32_t sbase = smem_u32(smem);

    const int tid  = threadIdx.x;
    const int wid  = tid >> 5;
    const int lane = tid & 31;
    const int nb   = blockIdx.x;
    const int m0   = nb * BM;

    // 8 warps: 2 row bands x 4 col groups; warp tile 32x16
    const int wr = (wid >> 2) * 32;
    const int wc = (wid & 3) * 16;
    const int qr = lane >> 2;
    const int qc = lane & 3;

    // mbarriers: full[s] at sbase + s*8 (count 1, tx); consumed[s] at +64+s*8 (count 8)
    if (tid == 0) {
#pragma unroll
        for (int s = 0; s < NSTAGE; s++) {
            mbar_init(sbase + s * 8, 1);
            mbar_init(sbase + 64 + s * 8, 8);
        }
    }
    __syncthreads();

    auto issue = [&](int chunk) {
        const int s = chunk & (NSTAGE - 1);
        const uint32_t stg = sbase + SM_BASE + s * STAGE_BYTES;
        const uint32_t mb  = sbase + s * 8;
        mbar_expect(mb, TX_BYTES);
        bulk_g2s(stg, g_x16 + ((size_t)nb * NCHUNK + chunk) * A_U32, A_BYTES, mb);
        bulk_g2s(stg + A_BYTES, g_B + (size_t)chunk * B_U32, B_BYTES, mb);
    };

    if (tid == 0) {
#pragma unroll
        for (int c = 0; c < NSTAGE; c++) issue(c);
    }

    float accM[2][2][4];
#pragma unroll
    for (int i = 0; i < 2; i++)
#pragma unroll
        for (int j = 0; j < 2; j++)
#pragma unroll
            for (int k = 0; k < 4; k++) accM[i][j][k] = 0.0f;

    for (int c = 0; c < NCHUNK; c++) {
        const int s = c & (NSTAGE - 1);
        const int r = c >> 2;              // round

        mbar_wait(sbase + s * 8, r & 1);   // stage full

        const uint32_t* A16 = (const uint32_t*)(smem + SM_BASE + s * STAGE_BYTES);
        const uint32_t* Bh  = A16 + A_U32;

        float accL[2][2][4];
#pragma unroll
        for (int i = 0; i < 2; i++)
#pragma unroll
            for (int j = 0; j < 2; j++)
#pragma unroll
                for (int k = 0; k < 4; k++) accL[i][j][k] = 0.0f;

#pragma unroll
        for (int K = 0; K < 4; K++) {
            const int so = (K >> 1) * 16 + (K & 1) * 8 + 2 * qc;

            uint32_t a[2][4];
#pragma unroll
            for (int mt = 0; mt < 2; mt++) {
                const int r0 = wr + mt * 16 + qr;
                uint2 lo2 = *(const uint2*)(A16 + r0 * STR + so);
                uint2 hi2 = *(const uint2*)(A16 + (r0 + 8) * STR + so);
                a[mt][0] = lo2.x; a[mt][2] = lo2.y;
                a[mt][1] = hi2.x; a[mt][3] = hi2.y;
            }
            uint2 bh[2];
#pragma unroll
            for (int nt = 0; nt < 2; nt++) {
                const int n = wc + nt * 8 + qr;
                bh[nt] = *(const uint2*)(Bh + n * STR + so);
            }
#pragma unroll
            for (int mt = 0; mt < 2; mt++)
#pragma unroll
                for (int nt = 0; nt < 2; nt++)
                    mma_f16(accL[mt][nt], a[mt][0], a[mt][1], a[mt][2], a[mt][3],
                            bh[nt].x, bh[nt].y);
        }

#pragma unroll
        for (int i = 0; i < 2; i++)
#pragma unroll
            for (int j = 0; j < 2; j++)
#pragma unroll
                for (int k = 0; k < 4; k++) accM[i][j][k] += accL[i][j][k];

        if (lane == 0) mbar_arrive(sbase + 64 + s * 8);

        if (tid == 0 && c + NSTAGE < NCHUNK) {
            mbar_wait(sbase + 64 + s * 8, r & 1);
            issue(c + NSTAGE);
        }
    }

    __syncthreads();   // all MMA reads done before overlaying smem

    // ---- stage logits into smem overlay ----
    float (*ls)[E_DIM + 2] = (float (*)[E_DIM + 2])smem;
#pragma unroll
    for (int mt = 0; mt < 2; mt++)
#pragma unroll
        for (int nt = 0; nt < 2; nt++) {
            int rr = wr + mt * 16 + qr;
            int cc = wc + nt * 8 + qc * 2;
            ls[rr][cc]         = accM[mt][nt][0];
            ls[rr][cc + 1]     = accM[mt][nt][1];
            ls[rr + 8][cc]     = accM[mt][nt][2];
            ls[rr + 8][cc + 1] = accM[mt][nt][3];
        }
    __syncthreads();

    // ---- epilogue: one warp per row (8 warps, 64 rows -> 8 each) ----
    const unsigned FULL = 0xFFFFFFFFu;

    auto wtop2 = [&](float pa, int ia, float pb, int ib,
                     float& V1, int& I1, float& V2, int& I2) {
        float v1, v2; int i1, i2;
        if (pa >= pb) { v1 = pa; i1 = ia; v2 = pb; i2 = ib; }
        else          { v1 = pb; i1 = ib; v2 = pa; i2 = ia; }
#pragma unroll
        for (int off = 16; off > 0; off >>= 1) {
            float ov1 = __shfl_xor_sync(FULL, v1, off);
            int   oi1 = __shfl_xor_sync(FULL, i1, off);
            float ov2 = __shfl_xor_sync(FULL, v2, off);
            int   oi2 = __shfl_xor_sync(FULL, i2, off);
            bool o_first = (ov1 > v1) || (ov1 == v1 && oi1 < i1);
            float n1, n2; int ni1, ni2;
            if (o_first) {
                n1 = ov1; ni1 = oi1;
                bool aa = (v1 > ov2) || (v1 == ov2 && i1 < oi2);
                if (aa) { n2 = v1;  ni2 = i1;  } else { n2 = ov2; ni2 = oi2; }
            } else {
                n1 = v1; ni1 = i1;
                bool aa = (ov1 > v2) || (ov1 == v2 && oi1 < i2);
                if (aa) { n2 = ov1; ni2 = oi1; } else { n2 = v2;  ni2 = i2;  }
            }
            v1 = n1; i1 = ni1; v2 = n2; i2 = ni2;
        }
        V1 = v1; I1 = i1; V2 = v2; I2 = i2;
    };

    for (int rrow = wid; rrow < BM; rrow += 8) {
        float l1 = ls[rrow][lane];
        float l2 = ls[rrow][lane + 32];

        float m = fmaxf(l1, l2);
#pragma unroll
        for (int off = 16; off > 0; off >>= 1)
            m = fmaxf(m, __shfl_xor_sync(FULL, m, off));

        float e1 = expf(l1 - m);
        float e2 = expf(l2 - m);

        float s = e1 + e2;
#pragma unroll
        for (int off = 16; off > 0; off >>= 1)
            s += __shfl_xor_sync(FULL, s, off);
        float inv = 1.0f / s;

        float pa = e1 * inv;
        float pb = e2 * inv;

        const int row = m0 + rrow;
        probs_out[(size_t)row * E_DIM + lane]      = pa;
        probs_out[(size_t)row * E_DIM + lane + 32] = pb;

        float v1, v2, v3, v4;
        int i1, i2, i3, i4;
        wtop2(pa, lane, pb, lane + 32, v1, i1, v2, i2);

        float pa2 = (lane == i1 || lane == i2) ? -1.0f : pa;
        float pb2 = (lane + 32 == i1 || lane + 32 == i2) ? -1.0f : pb;
        wtop2(pa2, lane, pb2, lane + 32, v3, i3, v4, i4);

        bool ambiguous = ((v1 - v2) < TAU) || ((v2 - v3) < TAU);

        if (!ambiguous) {
            if (lane == 0) {
                float denom = v1 + v2 + 1e-9f;
                idx_out[(size_t)row * 2 + 0] = (float)i1;
                idx_out[(size_t)row * 2 + 1] = (float)i2;
                w_out[(size_t)row * 2 + 0]   = v1 / denom;
                w_out[(size_t)row * 2 + 1]   = v2 / denom;
            }
        } else {
            const float* xr = x + (size_t)row * D_DIM;
            const float* w0 = W + (size_t)i1 * D_DIM;
            const float* w1 = W + (size_t)i2 * D_DIM;
            const float* w2 = W + (size_t)i3 * D_DIM;
            const float* w3 = W + (size_t)i4 * D_DIM;

            float d0 = 0.f, d1 = 0.f, d2 = 0.f, d3 = 0.f;
            for (int k = lane * 4; k < D_DIM; k += 128) {
                float4 xv = *(const float4*)(xr + k);
                float4 a  = *(const float4*)(w0 + k);
                float4 b  = *(const float4*)(w1 + k);
                float4 cc = *(const float4*)(w2 + k);
                float4 dd = *(const float4*)(w3 + k);
                d0 = fmaf(xv.x, a.x,  fmaf(xv.y, a.y,  fmaf(xv.z, a.z,  fmaf(xv.w, a.w,  d0))));
                d1 = fmaf(xv.x, b.x,  fmaf(xv.y, b.y,  fmaf(xv.z, b.z,  fmaf(xv.w, b.w,  d1))));
                d2 = fmaf(xv.x, cc.x, fmaf(xv.y, cc.y, fmaf(xv.z, cc.z, fmaf(xv.w, cc.w, d2))));
                d3 = fmaf(xv.x, dd.x, fmaf(xv.y, dd.y, fmaf(xv.z, dd.z, fmaf(xv.w, dd.w, d3))));
            }
#pragma unroll
            for (int off = 16; off > 0; off >>= 1) {
                d0 += __shfl_xor_sync(FULL, d0, off);
                d1 += __shfl_xor_sync(FULL, d1, off);
                d2 += __shfl_xor_sync(FULL, d2, off);
                d3 += __shfl_xor_sync(FULL, d3, off);
            }
            if (lane == 0) {
                float l[4]  = {d0, d1, d2, d3};
                int   id[4] = {i1, i2, i3, i4};
#pragma unroll
                for (int i = 0; i < 2; i++) {
                    int best = i;
#pragma unroll
                    for (int j = i + 1; j < 4; j++) {
                        if ((l[j] > l[best]) || (l[j] == l[best] && id[j] < id[best])) best = j;
                    }
                    float tl = l[i]; l[i] = l[best]; l[best] = tl;
                    int ti = id[i]; id[i] = id[best]; id[best] = ti;
                }
                float mm  = fmaxf(l[0], l[1]);
                float ee1 = expf(l[0] - mm);
                float ee2 = expf(l[1] - mm);
                float w1v = ee1 / (ee1 + ee2);
                idx_out[(size_t)row * 2 + 0] = (float)id[0];
                idx_out[(size_t)row * 2 + 1] = (float)id[1];
                w_out[(size_t)row * 2 + 0]   = w1v;
                w_out[(size_t)row * 2 + 1]   = 1.0f - w1v;
            }
        }
    }
}

extern "C" void kernel_launch(void* const* d_in, const int* in_sizes, int n_in,
                              void* d_out, int out_size)
{
    const float* x = (const float*)d_in[0];
    const float* W = (const float*)d_in[1];
    const int N = in_sizes[0] / D_DIM;   // 16384

    float* out   = (float*)d_out;
    float* probs = out;
    float* idx   = out + (size_t)N * E_DIM;
    float* wts   = out + (size_t)N * E_DIM + (size_t)N * 2;

    cudaFuncSetAttribute(router_kernel,
                         cudaFuncAttributeMaxDynamicSharedMemorySize, SMEM_BYTES);

    prep_kernel<<<NBLK * NCHUNK, 256>>>(x, W);
    router_kernel<<<N / BM, THREADS, SMEM_BYTES>>>(x, W, probs, idx, wts);
}

// round 13
// speedup vs baseline: 1.3236x; 1.0486x over previous
#include <cuda_runtime.h>
#include <cuda_fp16.h>
#include <cstdint>
#include <math.h>

// Router: logits = x @ W^T (N=16384, D=2048, E=64), softmax, top-2, renorm.
// Output fp32 concat: probs [N*64] | indices [N*2] | weights [N*2]
//
// R13: R12 + two fixes from the profile:
//  - STR 36 -> 40 u32: LDS.64 fragment loads become bank-conflict-free
//    (8*qr + 2*qc distinct per phase); R12's stride-36 had 2-way conflicts
//    on every frag load (L1 44.5%).
//  - producer warp specialization: 288 threads = 8 compute warps + 1
//    producer warp that owns all mbar_expect/bulk issues; compute warps
//    never block on the consumed barrier.

#define D_DIM 2048
#define E_DIM 64
#define BM 64
#define BK 64
#define THREADS 288
#define NCHUNK (D_DIM / BK)   // 32
#define NSTAGE 4
#define N_ROWS 16384
#define NBLK (N_ROWS / BM)    // 256
#define TAU 2e-3f

#define STR 40                                   // u32 stride per row (32 + pad 8)
#define A_U32 (BM * STR)                         // 2560  (10240 B)
#define B_U32 (64 * STR)                         // 2560  (10240 B)
#define A_BYTES (A_U32 * 4)
#define B_BYTES (B_U32 * 4)
#define STAGE_BYTES (A_BYTES + B_BYTES)          // 20480
#define SM_BASE 1024
#define SMEM_BYTES (SM_BASE + NSTAGE * STAGE_BYTES)   // 82944
#define TX_BYTES STAGE_BYTES

// g_x16[nb64][chunk] : 10KB blob = 64 rows x 40 u32 (permuted fp16x2 slots, 8 pad)
__device__ uint32_t g_x16[(size_t)NBLK * NCHUNK * A_U32];
// g_B[chunk] : 10KB blob = 64 experts x 40 u32 (fp16, single term)
__device__ uint32_t g_B[(size_t)NCHUNK * B_U32];

__device__ __forceinline__ uint32_t smem_u32(const void* p) {
    uint32_t a;
    asm("{ .reg .u64 t; cvta.to.shared.u64 t, %1; cvt.u32.u64 %0, t; }" : "=r"(a) : "l"(p));
    return a;
}
__device__ __forceinline__ uint32_t h2pack(float a, float b) {
    __half2 h = __floats2half2_rn(a, b);
    return *(uint32_t*)&h;
}
__device__ __forceinline__ void mma_f16(float* c,
                                        uint32_t a0, uint32_t a1, uint32_t a2, uint32_t a3,
                                        uint32_t b0, uint32_t b1) {
    asm volatile(
        "mma.sync.aligned.m16n8k16.row.col.f32.f16.f16.f32 "
        "{%0,%1,%2,%3}, {%4,%5,%6,%7}, {%8,%9}, {%0,%1,%2,%3};"
        : "+f"(c[0]), "+f"(c[1]), "+f"(c[2]), "+f"(c[3])
        : "r"(a0), "r"(a1), "r"(a2), "r"(a3), "r"(b0), "r"(b1));
}
__device__ __forceinline__ void mbar_init(uint32_t m, uint32_t cnt) {
    asm volatile("mbarrier.init.shared.b64 [%0], %1;" :: "r"(m), "r"(cnt) : "memory");
}
__device__ __forceinline__ void mbar_arrive(uint32_t m) {
    asm volatile("mbarrier.arrive.shared.b64 _, [%0];" :: "r"(m) : "memory");
}
__device__ __forceinline__ void mbar_expect(uint32_t m, uint32_t tx) {
    asm volatile("mbarrier.arrive.expect_tx.shared.b64 _, [%0], %1;" :: "r"(m), "r"(tx) : "memory");
}
__device__ __forceinline__ void bulk_g2s(uint32_t dst, const void* src, uint32_t bytes, uint32_t mbar) {
    asm volatile(
        "cp.async.bulk.shared::cluster.global.mbarrier::complete_tx::bytes [%0], [%1], %2, [%3];"
        :: "r"(dst), "l"(src), "r"(bytes), "r"(mbar) : "memory");
}
__device__ __forceinline__ void mbar_wait(uint32_t m, uint32_t parity) {
    uint32_t done;
    asm volatile(
        "{\n\t.reg .pred p;\n\t"
        "mbarrier.try_wait.parity.acquire.cta.shared::cta.b64 p, [%1], %2;\n\t"
        "selp.b32 %0, 1, 0, p;\n\t}"
        : "=r"(done) : "r"(m), "r"(parity) : "memory");
    if (!done) {
        asm volatile(
            "{\n\t.reg .pred P1;\n\t"
            "W_%=:\n\t"
            "mbarrier.try_wait.parity.acquire.cta.shared::cta.b64 P1, [%0], %1, 0x989680;\n\t"
            "@P1 bra.uni DN_%=;\n\t"
            "bra.uni W_%=;\n\t"
            "DN_%=:\n\t}"
            :: "r"(m), "r"(parity) : "memory");
    }
}

// ---- Kernel 1: prep. grid 8192 x 256 threads.
// Each block builds one g_x16 blob (nb = b>>5, chunk = b&31).
// Blocks 0-7 additionally build g_B.
__global__ __launch_bounds__(256, 4)
void prep_kernel(const float* __restrict__ x, const float* __restrict__ W)
{
    const int b     = blockIdx.x;
    const int tid   = threadIdx.x;
    const int chunk = b & (NCHUNK - 1);
    const int nb    = b >> 5;

    // x conversion: thread -> (row = tid>>2, quad = tid&3)
    {
        const int lrow = tid >> 2;
        const int clq  = tid & 3;
        const int ck0  = (clq & 1) * 4 + (clq >> 1) * 16;

        const float* src = x + (size_t)(nb * BM + lrow) * D_DIM + chunk * BK;
        uint32_t* dst = g_x16 + ((size_t)b * BM + lrow) * STR;

#pragma unroll
        for (int sub = 0; sub < 2; sub++) {
            const float* p = src + 32 * sub + ck0;
            float4 f0 = *(const float4*)(p);
            float4 f1 = *(const float4*)(p + 8);
            uint4 v;
            v.x = h2pack(f0.x, f0.y);
            v.y = h2pack(f1.x, f1.y);
            v.z = h2pack(f0.z, f0.w);
            v.w = h2pack(f1.z, f1.w);
            *(uint4*)(dst + sub * 16 + clq * 4) = v;
        }
        // zero the pad so reads are deterministic
        if (clq == 0) {
            *(uint4*)(dst + 32) = make_uint4(0, 0, 0, 0);
            *(uint4*)(dst + 36) = make_uint4(0, 0, 0, 0);
        }
    }

    // W split (single fp16 term): blocks 0-7, 256 threads each -> 2048 items
    if (b < 8) {
        const int g  = b * 256 + tid;       // 0..2047
        const int wc = g >> 6;              // chunk
        const int e  = g & 63;

        const float* src = W + (size_t)e * D_DIM + wc * BK;
        float v[64];
#pragma unroll
        for (int i = 0; i < 16; i++) {
            float4 f = *(const float4*)(src + 4 * i);
            v[4 * i] = f.x; v[4 * i + 1] = f.y; v[4 * i + 2] = f.z; v[4 * i + 3] = f.w;
        }
        uint32_t hi[32];
#pragma unroll
        for (int sub = 0; sub < 2; sub++) {
#pragma unroll
            for (int s = 0; s < 16; s++) {
                int bb = s >> 3;
                int s8 = s & 7;
                int pl = (s8 & 1) ? ((s8 >> 1) + 4) : (s8 >> 1);
                int k  = 32 * sub + bb * 16 + 2 * pl;
                hi[sub * 16 + s] = h2pack(v[k], v[k + 1]);
            }
        }
        uint32_t* dh = g_B + (size_t)wc * B_U32 + e * STR;
#pragma unroll
        for (int i = 0; i < 8; i++)
            *(uint4*)(dh + 4 * i) = *(uint4*)(hi + 4 * i);
        *(uint4*)(dh + 32) = make_uint4(0, 0, 0, 0);
        *(uint4*)(dh + 36) = make_uint4(0, 0, 0, 0);
    }
}

// ---- Kernel 2: router GEMM + softmax + top-2 (+ inline exact refine) ----
__global__ __launch_bounds__(THREADS, 2)
void router_kernel(const float* __restrict__ x,
                   const float* __restrict__ W,
                   float* __restrict__ probs_out,
                   float* __restrict__ idx_out,
                   float* __restrict__ w_out)
{
    extern __shared__ char smem[];
    const uint32_t sbase = smem_u32(smem);

    const int tid  = threadIdx.x;
    const int wid  = tid >> 5;          // 0..8 (8 = producer warp)
    const int lane = tid & 31;
    const int nb   = blockIdx.x;
    const int m0   = nb * BM;

    // compute warps 0-7: 2 row bands x 4 col groups; warp tile 32x16
    const int wr = (wid >> 2) * 32;
    const int wc = (wid & 3) * 16;
    const int qr = lane >> 2;
    const int qc = lane & 3;

    // mbarriers: full[s] at sbase + s*8 (count 1, tx); consumed[s] at +64+s*8 (count 8)
    if (tid == 0) {
#pragma unroll
        for (int s = 0; s < NSTAGE; s++) {
            mbar_init(sbase + s * 8, 1);
            mbar_init(sbase + 64 + s * 8, 8);
        }
    }
    __syncthreads();

    if (wid == 8) {
        // ---- producer warp ----
        if (lane == 0) {
            auto issue = [&](int chunk) {
                const int s = chunk & (NSTAGE - 1);
                const uint32_t stg = sbase + SM_BASE + s * STAGE_BYTES;
                const uint32_t mb  = sbase + s * 8;
                mbar_expect(mb, TX_BYTES);
                bulk_g2s(stg, g_x16 + ((size_t)nb * NCHUNK + chunk) * A_U32, A_BYTES, mb);
                bulk_g2s(stg + A_BYTES, g_B + (size_t)chunk * B_U32, B_BYTES, mb);
            };
#pragma unroll
            for (int c = 0; c < NSTAGE; c++) issue(c);
            int ph0 = 0, ph1 = 0, ph2 = 0, ph3 = 0;
            for (int c = NSTAGE; c < NCHUNK; c++) {
                const int s = c & (NSTAGE - 1);
                int& ph = (s == 0) ? ph0 : (s == 1) ? ph1 : (s == 2) ? ph2 : ph3;
                mbar_wait(sbase + 64 + s * 8, ph);
                ph ^= 1;
                issue(c);
            }
        }
    }

    float accM[2][2][4];
#pragma unroll
    for (int i = 0; i < 2; i++)
#pragma unroll
        for (int j = 0; j < 2; j++)
#pragma unroll
            for (int k = 0; k < 4; k++) accM[i][j][k] = 0.0f;

    if (wid < 8) {
        // ---- consumer mainloop ----
        for (int c = 0; c < NCHUNK; c++) {
            const int s = c & (NSTAGE - 1);
            const int r = c >> 2;

            mbar_wait(sbase + s * 8, r & 1);   // stage full

            const uint32_t* A16 = (const uint32_t*)(smem + SM_BASE + s * STAGE_BYTES);
            const uint32_t* Bh  = A16 + A_U32;

            float accL[2][2][4];
#pragma unroll
            for (int i = 0; i < 2; i++)
#pragma unroll
                for (int j = 0; j < 2; j++)
#pragma unroll
                    for (int k = 0; k < 4; k++) accL[i][j][k] = 0.0f;

#pragma unroll
            for (int K = 0; K < 4; K++) {
                const int so = (K >> 1) * 16 + (K & 1) * 8 + 2 * qc;

                uint32_t a[2][4];
#pragma unroll
                for (int mt = 0; mt < 2; mt++) {
                    const int r0 = wr + mt * 16 + qr;
                    uint2 lo2 = *(const uint2*)(A16 + r0 * STR + so);
                    uint2 hi2 = *(const uint2*)(A16 + (r0 + 8) * STR + so);
                    a[mt][0] = lo2.x; a[mt][2] = lo2.y;
                    a[mt][1] = hi2.x; a[mt][3] = hi2.y;
                }
                uint2 bh[2];
#pragma unroll
                for (int nt = 0; nt < 2; nt++) {
                    const int n = wc + nt * 8 + qr;
                    bh[nt] = *(const uint2*)(Bh + n * STR + so);
                }
#pragma unroll
                for (int mt = 0; mt < 2; mt++)
#pragma unroll
                    for (int nt = 0; nt < 2; nt++)
                        mma_f16(accL[mt][nt], a[mt][0], a[mt][1], a[mt][2], a[mt][3],
                                bh[nt].x, bh[nt].y);
            }

#pragma unroll
            for (int i = 0; i < 2; i++)
#pragma unroll
                for (int j = 0; j < 2; j++)
#pragma unroll
                    for (int k = 0; k < 4; k++) accM[i][j][k] += accL[i][j][k];

            if (lane == 0) mbar_arrive(sbase + 64 + s * 8);
        }
    }

    __syncthreads();   // all MMA reads done before overlaying smem

    // ---- stage logits into smem overlay (compute warps only) ----
    float (*ls)[E_DIM + 2] = (float (*)[E_DIM + 2])smem;
    if (wid < 8) {
#pragma unroll
        for (int mt = 0; mt < 2; mt++)
#pragma unroll
            for (int nt = 0; nt < 2; nt++) {
                int rr = wr + mt * 16 + qr;
                int cc = wc + nt * 8 + qc * 2;
                ls[rr][cc]         = accM[mt][nt][0];
                ls[rr][cc + 1]     = accM[mt][nt][1];
                ls[rr + 8][cc]     = accM[mt][nt][2];
                ls[rr + 8][cc + 1] = accM[mt][nt][3];
            }
    }
    __syncthreads();

    // ---- epilogue: one warp per row (8 compute warps, 8 rows each) ----
    const unsigned FULL = 0xFFFFFFFFu;

    auto wtop2 = [&](float pa, int ia, float pb, int ib,
                     float& V1, int& I1, float& V2, int& I2) {
        float v1, v2; int i1, i2;
        if (pa >= pb) { v1 = pa; i1 = ia; v2 = pb; i2 = ib; }
        else          { v1 = pb; i1 = ib; v2 = pa; i2 = ia; }
#pragma unroll
        for (int off = 16; off > 0; off >>= 1) {
            float ov1 = __shfl_xor_sync(FULL, v1, off);
            int   oi1 = __shfl_xor_sync(FULL, i1, off);
            float ov2 = __shfl_xor_sync(FULL, v2, off);
            int   oi2 = __shfl_xor_sync(FULL, i2, off);
            bool o_first = (ov1 > v1) || (ov1 == v1 && oi1 < i1);
            float n1, n2; int ni1, ni2;
            if (o_first) {
                n1 = ov1; ni1 = oi1;
                bool aa = (v1 > ov2) || (v1 == ov2 && i1 < oi2);
                if (aa) { n2 = v1;  ni2 = i1;  } else { n2 = ov2; ni2 = oi2; }
            } else {
                n1 = v1; ni1 = i1;
                bool aa = (ov1 > v2) || (ov1 == v2 && oi1 < i2);
                if (aa) { n2 = ov1; ni2 = oi1; } else { n2 = v2;  ni2 = i2;  }
            }
            v1 = n1; i1 = ni1; v2 = n2; i2 = ni2;
        }
        V1 = v1; I1 = i1; V2 = v2; I2 = i2;
    };

    if (wid < 8)
    for (int rrow = wid; rrow < BM; rrow += 8) {
        float l1 = ls[rrow][lane];
        float l2 = ls[rrow][lane + 32];

        float m = fmaxf(l1, l2);
#pragma unroll
        for (int off = 16; off > 0; off >>= 1)
            m = fmaxf(m, __shfl_xor_sync(FULL, m, off));

        float e1 = expf(l1 - m);
        float e2 = expf(l2 - m);

        float s = e1 + e2;
#pragma unroll
        for (int off = 16; off > 0; off >>= 1)
            s += __shfl_xor_sync(FULL, s, off);
        float inv = 1.0f / s;

        float pa = e1 * inv;
        float pb = e2 * inv;

        const int row = m0 + rrow;
        probs_out[(size_t)row * E_DIM + lane]      = pa;
        probs_out[(size_t)row * E_DIM + lane + 32] = pb;

        float v1, v2, v3, v4;
        int i1, i2, i3, i4;
        wtop2(pa, lane, pb, lane + 32, v1, i1, v2, i2);

        float pa2 = (lane == i1 || lane == i2) ? -1.0f : pa;
        float pb2 = (lane + 32 == i1 || lane + 32 == i2) ? -1.0f : pb;
        wtop2(pa2, lane, pb2, lane + 32, v3, i3, v4, i4);

        bool ambiguous = ((v1 - v2) < TAU) || ((v2 - v3) < TAU);

        if (!ambiguous) {
            if (lane == 0) {
                float denom = v1 + v2 + 1e-9f;
                idx_out[(size_t)row * 2 + 0] = (float)i1;
                idx_out[(size_t)row * 2 + 1] = (float)i2;
                w_out[(size_t)row * 2 + 0]   = v1 / denom;
                w_out[(size_t)row * 2 + 1]   = v2 / denom;
            }
        } else {
            const float* xr = x + (size_t)row * D_DIM;
            const float* w0 = W + (size_t)i1 * D_DIM;
            const float* w1 = W + (size_t)i2 * D_DIM;
            const float* w2 = W + (size_t)i3 * D_DIM;
            const float* w3 = W + (size_t)i4 * D_DIM;

            float d0 = 0.f, d1 = 0.f, d2 = 0.f, d3 = 0.f;
            for (int k = lane * 4; k < D_DIM; k += 128) {
                float4 xv = *(const float4*)(xr + k);
                float4 a  = *(const float4*)(w0 + k);
                float4 b  = *(const float4*)(w1 + k);
                float4 cc = *(const float4*)(w2 + k);
                float4 dd = *(const float4*)(w3 + k);
                d0 = fmaf(xv.x, a.x,  fmaf(xv.y, a.y,  fmaf(xv.z, a.z,  fmaf(xv.w, a.w,  d0))));
                d1 = fmaf(xv.x, b.x,  fmaf(xv.y, b.y,  fmaf(xv.z, b.z,  fmaf(xv.w, b.w,  d1))));
                d2 = fmaf(xv.x, cc.x, fmaf(xv.y, cc.y, fmaf(xv.z, cc.z, fmaf(xv.w, cc.w, d2))));
                d3 = fmaf(xv.x, dd.x, fmaf(xv.y, dd.y, fmaf(xv.z, dd.z, fmaf(xv.w, dd.w, d3))));
            }
#pragma unroll
            for (int off = 16; off > 0; off >>= 1) {
                d0 += __shfl_xor_sync(FULL, d0, off);
                d1 += __shfl_xor_sync(FULL, d1, off);
                d2 += __shfl_xor_sync(FULL, d2, off);
                d3 += __shfl_xor_sync(FULL, d3, off);
            }
            if (lane == 0) {
                float l[4]  = {d0, d1, d2, d3};
                int   id[4] = {i1, i2, i3, i4};
#pragma unroll
                for (int i = 0; i < 2; i++) {
                    int best = i;
#pragma unroll
                    for (int j = i + 1; j < 4; j++) {
                        if ((l[j] > l[best]) || (l[j] == l[best] && id[j] < id[best])) best = j;
                    }
                    float tl = l[i]; l[i] = l[best]; l[best] = tl;
                    int ti = id[i]; id[i] = id[best]; id[best] = ti;
                }
                float mm  = fmaxf(l[0], l[1]);
                float ee1 = expf(l[0] - mm);
                float ee2 = expf(l[1] - mm);
                float w1v = ee1 / (ee1 + ee2);
                idx_out[(size_t)row * 2 + 0] = (float)id[0];
                idx_out[(size_t)row * 2 + 1] = (float)id[1];
                w_out[(size_t)row * 2 + 0]   = w1v;
                w_out[(size_t)row * 2 + 1]   = 1.0f - w1v;
            }
        }
    }
}

extern "C" void kernel_launch(void* const* d_in, const int* in_sizes, int n_in,
                              void* d_out, int out_size)
{
    const float* x = (const float*)d_in[0];
    const float* W = (const float*)d_in[1];
    const int N = in_sizes[0] / D_DIM;   // 16384

    float* out   = (float*)d_out;
    float* probs = out;
    float* idx   = out + (size_t)N * E_DIM;
    float* wts   = out + (size_t)N * E_DIM + (size_t)N * 2;

    cudaFuncSetAttribute(router_kernel,
                         cudaFuncAttributeMaxDynamicSharedMemorySize, SMEM_BYTES);

    prep_kernel<<<NBLK * NCHUNK, 256>>>(x, W);
    router_kernel<<<N / BM, THREADS, SMEM_BYTES>>>(x, W, probs, idx, wts);
}

// round 14
// speedup vs baseline: 1.3902x; 1.0503x over previous
#include <cuda_runtime.h>
#include <cuda_fp16.h>
#include <cstdint>
#include <math.h>

// Router: logits = x @ W^T (N=16384, D=2048, E=64), softmax, top-2, renorm.
// Output fp32 concat: probs [N*64] | indices [N*2] | weights [N*2]
//
// R14: R13 with BK 64 -> 128: 16 chunks, NSTAGE=2, 36KB stages. Same smem
// and bytes-in-flight, HALF the mbarrier wait/arrive/wake events, 2x work
// per wake (the R13 profile showed event cadence, not any pipe, binding).
// Row stride 72 u32 (mod32=8, frag-conflict-free). Producer warp owns all
// bulk issues. Single-fp16 W, chunk-local fold, inline exact refine.

#define D_DIM 2048
#define E_DIM 64
#define BM 64
#define BK 128
#define THREADS 288
#define NCHUNK (D_DIM / BK)   // 16
#define NSTAGE 2
#define N_ROWS 16384
#define NBLK (N_ROWS / BM)    // 256
#define TAU 2e-3f

#define STR 72                                   // u32 stride per row (64 + pad 8)
#define A_U32 (BM * STR)                         // 4608  (18432 B)
#define B_U32 (64 * STR)                         // 4608  (18432 B)
#define A_BYTES (A_U32 * 4)
#define B_BYTES (B_U32 * 4)
#define STAGE_BYTES (A_BYTES + B_BYTES)          // 36864
#define SM_BASE 1024
#define SMEM_BYTES (SM_BASE + NSTAGE * STAGE_BYTES)   // 74752
#define TX_BYTES STAGE_BYTES

// g_x16[nb][chunk] : 18KB blob = 64 rows x 72 u32 (permuted fp16x2 slots, 8 pad)
__device__ uint32_t g_x16[(size_t)NBLK * NCHUNK * A_U32];
// g_B[chunk] : 18KB blob = 64 experts x 72 u32 (fp16, single term)
__device__ uint32_t g_B[(size_t)NCHUNK * B_U32];

__device__ __forceinline__ uint32_t smem_u32(const void* p) {
    uint32_t a;
    asm("{ .reg .u64 t; cvta.to.shared.u64 t, %1; cvt.u32.u64 %0, t; }" : "=r"(a) : "l"(p));
    return a;
}
__device__ __forceinline__ uint32_t h2pack(float a, float b) {
    __half2 h = __floats2half2_rn(a, b);
    return *(uint32_t*)&h;
}
__device__ __forceinline__ void mma_f16(float* c,
                                        uint32_t a0, uint32_t a1, uint32_t a2, uint32_t a3,
                                        uint32_t b0, uint32_t b1) {
    asm volatile(
        "mma.sync.aligned.m16n8k16.row.col.f32.f16.f16.f32 "
        "{%0,%1,%2,%3}, {%4,%5,%6,%7}, {%8,%9}, {%0,%1,%2,%3};"
        : "+f"(c[0]), "+f"(c[1]), "+f"(c[2]), "+f"(c[3])
        : "r"(a0), "r"(a1), "r"(a2), "r"(a3), "r"(b0), "r"(b1));
}
__device__ __forceinline__ void mbar_init(uint32_t m, uint32_t cnt) {
    asm volatile("mbarrier.init.shared.b64 [%0], %1;" :: "r"(m), "r"(cnt) : "memory");
}
__device__ __forceinline__ void mbar_arrive(uint32_t m) {
    asm volatile("mbarrier.arrive.shared.b64 _, [%0];" :: "r"(m) : "memory");
}
__device__ __forceinline__ void mbar_expect(uint32_t m, uint32_t tx) {
    asm volatile("mbarrier.arrive.expect_tx.shared.b64 _, [%0], %1;" :: "r"(m), "r"(tx) : "memory");
}
__device__ __forceinline__ void bulk_g2s(uint32_t dst, const void* src, uint32_t bytes, uint32_t mbar) {
    asm volatile(
        "cp.async.bulk.shared::cluster.global.mbarrier::complete_tx::bytes [%0], [%1], %2, [%3];"
        :: "r"(dst), "l"(src), "r"(bytes), "r"(mbar) : "memory");
}
__device__ __forceinline__ void mbar_wait(uint32_t m, uint32_t parity) {
    uint32_t done;
    asm volatile(
        "{\n\t.reg .pred p;\n\t"
        "mbarrier.try_wait.parity.acquire.cta.shared::cta.b64 p, [%1], %2;\n\t"
        "selp.b32 %0, 1, 0, p;\n\t}"
        : "=r"(done) : "r"(m), "r"(parity) : "memory");
    if (!done) {
        asm volatile(
            "{\n\t.reg .pred P1;\n\t"
            "W_%=:\n\t"
            "mbarrier.try_wait.parity.acquire.cta.shared::cta.b64 P1, [%0], %1, 0x989680;\n\t"
            "@P1 bra.uni DN_%=;\n\t"
            "bra.uni W_%=;\n\t"
            "DN_%=:\n\t}"
            :: "r"(m), "r"(parity) : "memory");
    }
}

// ---- Kernel 1: prep. grid 4096 x 256 threads.
// Each block builds one g_x16 blob (nb = b>>4, chunk = b&15).
// Blocks 0-3 additionally build g_B (1024 (chunk,expert) items).
__global__ __launch_bounds__(256, 4)
void prep_kernel(const float* __restrict__ x, const float* __restrict__ W)
{
    const int b     = blockIdx.x;
    const int tid   = threadIdx.x;
    const int chunk = b & (NCHUNK - 1);
    const int nb    = b >> 4;

    // x conversion: thread -> (row = tid>>2, quad = tid&3), 4 subs of 32 k
    {
        const int lrow = tid >> 2;
        const int clq  = tid & 3;
        const int ck0  = (clq & 1) * 4 + (clq >> 1) * 16;

        const float* src = x + (size_t)(nb * BM + lrow) * D_DIM + chunk * BK;
        uint32_t* dst = g_x16 + ((size_t)b * BM + lrow) * STR;

#pragma unroll
        for (int sub = 0; sub < 4; sub++) {
            const float* p = src + 32 * sub + ck0;
            float4 f0 = *(const float4*)(p);
            float4 f1 = *(const float4*)(p + 8);
            uint4 v;
            v.x = h2pack(f0.x, f0.y);
            v.y = h2pack(f1.x, f1.y);
            v.z = h2pack(f0.z, f0.w);
            v.w = h2pack(f1.z, f1.w);
            *(uint4*)(dst + sub * 16 + clq * 4) = v;
        }
        // pad (slots 64-71) never read by frag loads; left unwritten
    }

    // W split (single fp16 term): blocks 0-3, 256 threads each -> 1024 items
    if (b < 4) {
        const int g  = b * 256 + tid;       // 0..1023
        const int wc = g >> 6;              // chunk 0..15
        const int e  = g & 63;

        const float* srcw = W + (size_t)e * D_DIM + wc * BK;
        uint32_t* dh = g_B + (size_t)wc * B_U32 + e * STR;

#pragma unroll
        for (int sub = 0; sub < 4; sub++) {
            float v[32];
#pragma unroll
            for (int i = 0; i < 8; i++) {
                float4 f = *(const float4*)(srcw + 32 * sub + 4 * i);
                v[4 * i] = f.x; v[4 * i + 1] = f.y; v[4 * i + 2] = f.z; v[4 * i + 3] = f.w;
            }
            uint32_t hi[16];
#pragma unroll
            for (int s = 0; s < 16; s++) {
                int bb = s >> 3;
                int s8 = s & 7;
                int pl = (s8 & 1) ? ((s8 >> 1) + 4) : (s8 >> 1);
                int k  = bb * 16 + 2 * pl;
                hi[s] = h2pack(v[k], v[k + 1]);
            }
#pragma unroll
            for (int i = 0; i < 4; i++)
                *(uint4*)(dh + sub * 16 + 4 * i) = *(uint4*)(hi + 4 * i);
        }
    }
}

// ---- Kernel 2: router GEMM + softmax + top-2 (+ inline exact refine) ----
__global__ __launch_bounds__(THREADS, 2)
void router_kernel(const float* __restrict__ x,
                   const float* __restrict__ W,
                   float* __restrict__ probs_out,
                   float* __restrict__ idx_out,
                   float* __restrict__ w_out)
{
    extern __shared__ char smem[];
    const uint32_t sbase = smem_u32(smem);

    const int tid  = threadIdx.x;
    const int wid  = tid >> 5;          // 0..8 (8 = producer warp)
    const int lane = tid & 31;
    const int nb   = blockIdx.x;
    const int m0   = nb * BM;

    // compute warps 0-7: 2 row bands x 4 col groups; warp tile 32x16
    const int wr = (wid >> 2) * 32;
    const int wc = (wid & 3) * 16;
    const int qr = lane >> 2;
    const int qc = lane & 3;

    // mbarriers: full[s] at sbase + s*8 (count 1, tx); consumed[s] at +64+s*8 (count 8)
    if (tid == 0) {
#pragma unroll
        for (int s = 0; s < NSTAGE; s++) {
            mbar_init(sbase + s * 8, 1);
            mbar_init(sbase + 64 + s * 8, 8);
        }
    }
    __syncthreads();

    if (wid == 8) {
        // ---- producer warp ----
        if (lane == 0) {
            auto issue = [&](int chunk) {
                const int s = chunk & (NSTAGE - 1);
                const uint32_t stg = sbase + SM_BASE + s * STAGE_BYTES;
                const uint32_t mb  = sbase + s * 8;
                mbar_expect(mb, TX_BYTES);
                bulk_g2s(stg, g_x16 + ((size_t)nb * NCHUNK + chunk) * A_U32, A_BYTES, mb);
                bulk_g2s(stg + A_BYTES, g_B + (size_t)chunk * B_U32, B_BYTES, mb);
            };
            issue(0);
            issue(1);
            int ph0 = 0, ph1 = 0;
            for (int c = NSTAGE; c < NCHUNK; c++) {
                const int s = c & (NSTAGE - 1);
                int& ph = (s == 0) ? ph0 : ph1;
                mbar_wait(sbase + 64 + s * 8, ph);
                ph ^= 1;
                issue(c);
            }
        }
    }

    float accM[2][2][4];
#pragma unroll
    for (int i = 0; i < 2; i++)
#pragma unroll
        for (int j = 0; j < 2; j++)
#pragma unroll
            for (int k = 0; k < 4; k++) accM[i][j][k] = 0.0f;

    if (wid < 8) {
        // ---- consumer mainloop: 16 chunks, 8 K-steps each ----
        for (int c = 0; c < NCHUNK; c++) {
            const int s = c & (NSTAGE - 1);

            mbar_wait(sbase + s * 8, (c >> 1) & 1);   // stage full

            const uint32_t* A16 = (const uint32_t*)(smem + SM_BASE + s * STAGE_BYTES);
            const uint32_t* Bh  = A16 + A_U32;

            float accL[2][2][4];
#pragma unroll
            for (int i = 0; i < 2; i++)
#pragma unroll
                for (int j = 0; j < 2; j++)
#pragma unroll
                    for (int k = 0; k < 4; k++) accL[i][j][k] = 0.0f;

#pragma unroll
            for (int K = 0; K < 8; K++) {
                const int so = (K >> 1) * 16 + (K & 1) * 8 + 2 * qc;

                uint32_t a[2][4];
#pragma unroll
                for (int mt = 0; mt < 2; mt++) {
                    const int r0 = wr + mt * 16 + qr;
                    uint2 lo2 = *(const uint2*)(A16 + r0 * STR + so);
                    uint2 hi2 = *(const uint2*)(A16 + (r0 + 8) * STR + so);
                    a[mt][0] = lo2.x; a[mt][2] = lo2.y;
                    a[mt][1] = hi2.x; a[mt][3] = hi2.y;
                }
                uint2 bh[2];
#pragma unroll
                for (int nt = 0; nt < 2; nt++) {
                    const int n = wc + nt * 8 + qr;
                    bh[nt] = *(const uint2*)(Bh + n * STR + so);
                }
#pragma unroll
                for (int mt = 0; mt < 2; mt++)
#pragma unroll
                    for (int nt = 0; nt < 2; nt++)
                        mma_f16(accL[mt][nt], a[mt][0], a[mt][1], a[mt][2], a[mt][3],
                                bh[nt].x, bh[nt].y);
            }

#pragma unroll
            for (int i = 0; i < 2; i++)
#pragma unroll
                for (int j = 0; j < 2; j++)
#pragma unroll
                    for (int k = 0; k < 4; k++) accM[i][j][k] += accL[i][j][k];

            if (lane == 0) mbar_arrive(sbase + 64 + s * 8);
        }
    }

    __syncthreads();   // all MMA reads done before overlaying smem

    // ---- stage logits into smem overlay (compute warps only) ----
    float (*ls)[E_DIM + 2] = (float (*)[E_DIM + 2])smem;
    if (wid < 8) {
#pragma unroll
        for (int mt = 0; mt < 2; mt++)
#pragma unroll
            for (int nt = 0; nt < 2; nt++) {
                int rr = wr + mt * 16 + qr;
                int cc = wc + nt * 8 + qc * 2;
                ls[rr][cc]         = accM[mt][nt][0];
                ls[rr][cc + 1]     = accM[mt][nt][1];
                ls[rr + 8][cc]     = accM[mt][nt][2];
                ls[rr + 8][cc + 1] = accM[mt][nt][3];
            }
    }
    __syncthreads();

    // ---- epilogue: one warp per row (8 compute warps, 8 rows each) ----
    const unsigned FULL = 0xFFFFFFFFu;

    auto wtop2 = [&](float pa, int ia, float pb, int ib,
                     float& V1, int& I1, float& V2, int& I2) {
        float v1, v2; int i1, i2;
        if (pa >= pb) { v1 = pa; i1 = ia; v2 = pb; i2 = ib; }
        else          { v1 = pb; i1 = ib; v2 = pa; i2 = ia; }
#pragma unroll
        for (int off = 16; off > 0; off >>= 1) {
            float ov1 = __shfl_xor_sync(FULL, v1, off);
            int   oi1 = __shfl_xor_sync(FULL, i1, off);
            float ov2 = __shfl_xor_sync(FULL, v2, off);
            int   oi2 = __shfl_xor_sync(FULL, i2, off);
            bool o_first = (ov1 > v1) || (ov1 == v1 && oi1 < i1);
            float n1, n2; int ni1, ni2;
            if (o_first) {
                n1 = ov1; ni1 = oi1;
                bool aa = (v1 > ov2) || (v1 == ov2 && i1 < oi2);
                if (aa) { n2 = v1;  ni2 = i1;  } else { n2 = ov2; ni2 = oi2; }
            } else {
                n1 = v1; ni1 = i1;
                bool aa = (ov1 > v2) || (ov1 == v2 && oi1 < i2);
                if (aa) { n2 = ov1; ni2 = oi1; } else { n2 = v2;  ni2 = i2;  }
            }
            v1 = n1; i1 = ni1; v2 = n2; i2 = ni2;
        }
        V1 = v1; I1 = i1; V2 = v2; I2 = i2;
    };

    if (wid < 8)
    for (int rrow = wid; rrow < BM; rrow += 8) {
        float l1 = ls[rrow][lane];
        float l2 = ls[rrow][lane + 32];

        float m = fmaxf(l1, l2);
#pragma unroll
        for (int off = 16; off > 0; off >>= 1)
            m = fmaxf(m, __shfl_xor_sync(FULL, m, off));

        float e1 = expf(l1 - m);
        float e2 = expf(l2 - m);

        float s = e1 + e2;
#pragma unroll
        for (int off = 16; off > 0; off >>= 1)
            s += __shfl_xor_sync(FULL, s, off);
        float inv = 1.0f / s;

        float pa = e1 * inv;
        float pb = e2 * inv;

        const int row = m0 + rrow;
        probs_out[(size_t)row * E_DIM + lane]      = pa;
        probs_out[(size_t)row * E_DIM + lane + 32] = pb;

        float v1, v2, v3, v4;
        int i1, i2, i3, i4;
        wtop2(pa, lane, pb, lane + 32, v1, i1, v2, i2);

        float pa2 = (lane == i1 || lane == i2) ? -1.0f : pa;
        float pb2 = (lane + 32 == i1 || lane + 32 == i2) ? -1.0f : pb;
        wtop2(pa2, lane, pb2, lane + 32, v3, i3, v4, i4);

        bool ambiguous = ((v1 - v2) < TAU) || ((v2 - v3) < TAU);

        if (!ambiguous) {
            if (lane == 0) {
                float denom = v1 + v2 + 1e-9f;
                idx_out[(size_t)row * 2 + 0] = (float)i1;
                idx_out[(size_t)row * 2 + 1] = (float)i2;
                w_out[(size_t)row * 2 + 0]   = v1 / denom;
                w_out[(size_t)row * 2 + 1]   = v2 / denom;
            }
        } else {
            const float* xr = x + (size_t)row * D_DIM;
            const float* w0 = W + (size_t)i1 * D_DIM;
            const float* w1 = W + (size_t)i2 * D_DIM;
            const float* w2 = W + (size_t)i3 * D_DIM;
            const float* w3 = W + (size_t)i4 * D_DIM;

            float d0 = 0.f, d1 = 0.f, d2 = 0.f, d3 = 0.f;
            for (int k = lane * 4; k < D_DIM; k += 128) {
                float4 xv = *(const float4*)(xr + k);
                float4 a  = *(const float4*)(w0 + k);
                float4 b  = *(const float4*)(w1 + k);
                float4 cc = *(const float4*)(w2 + k);
                float4 dd = *(const float4*)(w3 + k);
                d0 = fmaf(xv.x, a.x,  fmaf(xv.y, a.y,  fmaf(xv.z, a.z,  fmaf(xv.w, a.w,  d0))));
                d1 = fmaf(xv.x, b.x,  fmaf(xv.y, b.y,  fmaf(xv.z, b.z,  fmaf(xv.w, b.w,  d1))));
                d2 = fmaf(xv.x, cc.x, fmaf(xv.y, cc.y, fmaf(xv.z, cc.z, fmaf(xv.w, cc.w, d2))));
                d3 = fmaf(xv.x, dd.x, fmaf(xv.y, dd.y, fmaf(xv.z, dd.z, fmaf(xv.w, dd.w, d3))));
            }
#pragma unroll
            for (int off = 16; off > 0; off >>= 1) {
                d0 += __shfl_xor_sync(FULL, d0, off);
                d1 += __shfl_xor_sync(FULL, d1, off);
                d2 += __shfl_xor_sync(FULL, d2, off);
                d3 += __shfl_xor_sync(FULL, d3, off);
            }
            if (lane == 0) {
                float l[4]  = {d0, d1, d2, d3};
                int   id[4] = {i1, i2, i3, i4};
#pragma unroll
                for (int i = 0; i < 2; i++) {
                    int best = i;
#pragma unroll
                    for (int j = i + 1; j < 4; j++) {
                        if ((l[j] > l[best]) || (l[j] == l[best] && id[j] < id[best])) best = j;
                    }
                    float tl = l[i]; l[i] = l[best]; l[best] = tl;
                    int ti = id[i]; id[i] = id[best]; id[best] = ti;
                }
                float mm  = fmaxf(l[0], l[1]);
                float ee1 = expf(l[0] - mm);
                float ee2 = expf(l[1] - mm);
                float w1v = ee1 / (ee1 + ee2);
                idx_out[(size_t)row * 2 + 0] = (float)id[0];
                idx_out[(size_t)row * 2 + 1] = (float)id[1];
                w_out[(size_t)row * 2 + 0]   = w1v;
                w_out[(size_t)row * 2 + 1]   = 1.0f - w1v;
            }
        }
    }
}

extern "C" void kernel_launch(void* const* d_in, const int* in_sizes, int n_in,
                              void* d_out, int out_size)
{
    const float* x = (const float*)d_in[0];
    const float* W = (const float*)d_in[1];
    const int N = in_sizes[0] / D_DIM;   // 16384

    float* out   = (float*)d_out;
    float* probs = out;
    float* idx   = out + (size_t)N * E_DIM;
    float* wts   = out + (size_t)N * E_DIM + (size_t)N * 2;

    cudaFuncSetAttribute(router_kernel,
                         cudaFuncAttributeMaxDynamicSharedMemorySize, SMEM_BYTES);

    prep_kernel<<<NBLK * NCHUNK, 256>>>(x, W);
    router_kernel<<<N / BM, THREADS, SMEM_BYTES>>>(x, W, probs, idx, wts);
}